// round 1
// baseline (speedup 1.0000x reference)
#include <cuda_runtime.h>
#include <math.h>

#define T_SEQ  2048
#define BATCH  2
#define DMODEL 2048
#define NH     16
#define DHEAD  128
#define DCAT   128   // 64 sem + 64 geo concatenated

// ---------------- scratch (device globals: allocation-free) ----------------
__device__ float g_Qcat[(size_t)BATCH * NH * T_SEQ * DCAT];   // 32 MB
__device__ float g_Kcat[(size_t)BATCH * NH * T_SEQ * DCAT];   // 32 MB
__device__ float g_V  [(size_t)BATCH * NH * T_SEQ * DHEAD];   // 32 MB
__device__ float g_O  [(size_t)BATCH * T_SEQ * DMODEL];       // 32 MB

// ---------------- generic tiled GEMM with head-split epilogue ----------------
// C[m, col] = sum_k A[m,k] * W[k,col], written to
// out[((b*nheads + h)*T_SEQ + t)*ostride + dstart + d]
// where b=m/T_SEQ, t=m%T_SEQ, h=col/hd, d=col%hd, nheads=N/hd.
__global__ __launch_bounds__(256)
void gemm_kernel(const float* __restrict__ A, const float* __restrict__ W,
                 float* __restrict__ out,
                 int N, int K, int hd, int ostride, int dstart)
{
    const int bm = blockIdx.y * 64;
    const int bn = blockIdx.x * 64;

    __shared__ float As[16][64];   // [k][m]
    __shared__ float Ws[16][64];   // [k][n]

    const int tid = threadIdx.x;
    const int tx = tid % 16;       // n
    const int ty = tid / 16;       // m

    float acc[4][4] = {};

    const int ar  = tid >> 2;          // 0..63  (m within tile)
    const int ac4 = (tid & 3) * 4;     // 0,4,8,12 (k within tile)
    const int wr  = tid >> 4;          // 0..15  (k within tile)
    const int wc4 = (tid & 15) * 4;    // 0..60  (n within tile)

    for (int k0 = 0; k0 < K; k0 += 16) {
        float4 av = *(const float4*)&A[(size_t)(bm + ar) * K + k0 + ac4];
        As[ac4 + 0][ar] = av.x;
        As[ac4 + 1][ar] = av.y;
        As[ac4 + 2][ar] = av.z;
        As[ac4 + 3][ar] = av.w;
        *(float4*)&Ws[wr][wc4] =
            *(const float4*)&W[(size_t)(k0 + wr) * N + bn + wc4];
        __syncthreads();

#pragma unroll
        for (int k = 0; k < 16; k++) {
            float4 a = *(float4*)&As[k][ty * 4];
            float4 b = *(float4*)&Ws[k][tx * 4];
            float aa[4] = {a.x, a.y, a.z, a.w};
            float bb[4] = {b.x, b.y, b.z, b.w};
#pragma unroll
            for (int i = 0; i < 4; i++)
#pragma unroll
                for (int j = 0; j < 4; j++)
                    acc[i][j] += aa[i] * bb[j];
        }
        __syncthreads();
    }

    const int nheads = N / hd;
#pragma unroll
    for (int i = 0; i < 4; i++) {
        int m = bm + ty * 4 + i;
        int b = m / T_SEQ, t = m % T_SEQ;
#pragma unroll
        for (int j = 0; j < 4; j++) {
            int col = bn + tx * 4 + j;
            int h = col / hd, d = col % hd;
            out[(((size_t)b * nheads + h) * T_SEQ + t) * ostride + dstart + d] =
                acc[i][j];
        }
    }
}

// ---------------- RoPE + gate folding ----------------
// Qcat row layout: [0,64)=sem, [64,128)=geo. Fold scales into Q:
//   sem *= 2*sigmoid(g[h]) / sqrt(64);  geo = rope(geo) * (2-2*sigmoid) / sqrt(64)
// Kcat: geo part gets rope only.
__global__ void rope_gate_kernel(float* __restrict__ Qcat, float* __restrict__ Kcat,
                                 const float* __restrict__ gate_logit,
                                 const int* __restrict__ pos_off)
{
    int row  = blockIdx.x * 4 + (threadIdx.x >> 5);   // 0 .. B*NH*T-1
    int lane = threadIdx.x & 31;

    int t = row % T_SEQ;
    int h = (row / T_SEQ) % NH;

    float g = 1.f / (1.f + expf(-gate_logit[h]));
    float qs_scale = 2.f * g * 0.125f;            // 1/sqrt(64) = 0.125
    float qg_scale = (2.f - 2.f * g) * 0.125f;

    float freq = powf(10000.f, -(float)lane / 32.f);
    float ang  = (float)(t + pos_off[0]) * freq;
    float c = cosf(ang), s = sinf(ang);

    float* qp = Qcat + (size_t)row * DCAT;
    float* kp = Kcat + (size_t)row * DCAT;

    qp[lane]      *= qs_scale;
    qp[lane + 32] *= qs_scale;

    float x1 = qp[64 + lane], x2 = qp[96 + lane];
    qp[64 + lane] = (x1 * c - x2 * s) * qg_scale;
    qp[96 + lane] = (x2 * c + x1 * s) * qg_scale;

    float k1 = kp[64 + lane], k2 = kp[96 + lane];
    kp[64 + lane] = k1 * c - k2 * s;
    kp[96 + lane] = k2 * c + k1 * s;
}

// ---------------- flash attention (fp32, online softmax, causal) ----------------
#define BM 64
#define BN 64
// smem floats: Qs 64*128, Ks 64*128, Ss 64*68, m/l/corr 3*64
#define SMEM_FLASH ((2 * 64 * 128 + 64 * 68 + 3 * 64) * 4)

__global__ __launch_bounds__(256)
void flash_kernel(const float* __restrict__ Q, const float* __restrict__ Kc,
                  const float* __restrict__ V, float* __restrict__ Og)
{
    extern __shared__ float sm[];
    float* Qs     = sm;                     // [64][128]
    float* Ks     = sm + 64 * 128;          // [64][128]  (K tile, then V tile)
    float* Ss     = sm + 2 * 64 * 128;      // [64][68]
    float* m_s    = Ss + 64 * 68;
    float* l_s    = m_s + 64;
    float* corr_s = l_s + 64;

    const int qi = blockIdx.x;              // q tile index
    const int bh = blockIdx.y;              // b*NH + h
    const int q0 = qi * BM;

    const float* Qb = Q  + ((size_t)bh * T_SEQ + q0) * DCAT;
    const float* Kb = Kc + (size_t)bh * T_SEQ * DCAT;
    const float* Vb = V  + (size_t)bh * T_SEQ * DHEAD;

    const int tid = threadIdx.x;
    const int tx = tid % 16;                // 16 cols of 4 (S) / 8 (O)
    const int ty = tid / 16;                // 16 rows of 4

    for (int i = tid; i < 64 * 128 / 4; i += 256)
        ((float4*)Qs)[i] = ((const float4*)Qb)[i];
    if (tid < 64) { m_s[tid] = -1e30f; l_s[tid] = 0.f; }

    float acc[4][8];
#pragma unroll
    for (int i = 0; i < 4; i++)
#pragma unroll
        for (int j = 0; j < 8; j++) acc[i][j] = 0.f;

    __syncthreads();

    for (int kt = 0; kt <= qi; kt++) {
        const int k0 = kt * BN;

        // K tile -> smem
        for (int i = tid; i < 64 * 128 / 4; i += 256)
            ((float4*)Ks)[i] = ((const float4*)(Kb + (size_t)k0 * DCAT))[i];
        __syncthreads();

        // S = Q @ K^T  (scales already folded into Q)
        float s4[4][4] = {};
#pragma unroll 4
        for (int k = 0; k < DCAT; k += 4) {
            float4 a[4], b[4];
#pragma unroll
            for (int i = 0; i < 4; i++) a[i] = *(float4*)&Qs[(ty * 4 + i) * 128 + k];
#pragma unroll
            for (int j = 0; j < 4; j++) b[j] = *(float4*)&Ks[(tx * 4 + j) * 128 + k];
#pragma unroll
            for (int i = 0; i < 4; i++)
#pragma unroll
                for (int j = 0; j < 4; j++)
                    s4[i][j] += a[i].x * b[j].x + a[i].y * b[j].y +
                                a[i].z * b[j].z + a[i].w * b[j].w;
        }
        const bool diag = (kt == qi);
#pragma unroll
        for (int i = 0; i < 4; i++) {
            int r = ty * 4 + i;
#pragma unroll
            for (int j = 0; j < 4; j++) {
                int c = tx * 4 + j;
                float v = s4[i][j];
                if (diag && c > r) v = -1e30f;
                Ss[r * 68 + c] = v;
            }
        }
        __syncthreads();

        // online softmax (one thread per row)
        if (tid < 64) {
            int r = tid;
            float mold = m_s[r];
            float mx = mold;
#pragma unroll 8
            for (int j = 0; j < 64; j++) mx = fmaxf(mx, Ss[r * 68 + j]);
            float corr = __expf(mold - mx);
            float sum = 0.f;
#pragma unroll 8
            for (int j = 0; j < 64; j++) {
                float p = __expf(Ss[r * 68 + j] - mx);
                Ss[r * 68 + j] = p;
                sum += p;
            }
            l_s[r] = l_s[r] * corr + sum;
            m_s[r] = mx;
            corr_s[r] = corr;
        }
        __syncthreads();

        // rescale accumulators; load V tile over K tile
        float cr[4];
#pragma unroll
        for (int i = 0; i < 4; i++) cr[i] = corr_s[ty * 4 + i];
#pragma unroll
        for (int i = 0; i < 4; i++)
#pragma unroll
            for (int j = 0; j < 8; j++) acc[i][j] *= cr[i];

        for (int i = tid; i < 64 * 128 / 4; i += 256)
            ((float4*)Ks)[i] = ((const float4*)(Vb + (size_t)k0 * DHEAD))[i];
        __syncthreads();

        // O += P @ V   (rows ty*4+i, cols tx*8+j)
#pragma unroll 2
        for (int k = 0; k < BN; k += 4) {
            float pr[4][4];
#pragma unroll
            for (int i = 0; i < 4; i++) {
                float4 p4 = *(float4*)&Ss[(ty * 4 + i) * 68 + k];
                pr[i][0] = p4.x; pr[i][1] = p4.y; pr[i][2] = p4.z; pr[i][3] = p4.w;
            }
#pragma unroll
            for (int kk = 0; kk < 4; kk++) {
                float4 v0 = *(float4*)&Ks[(k + kk) * 128 + tx * 8];
                float4 v1 = *(float4*)&Ks[(k + kk) * 128 + tx * 8 + 4];
#pragma unroll
                for (int i = 0; i < 4; i++) {
                    float p = pr[i][kk];
                    acc[i][0] += p * v0.x; acc[i][1] += p * v0.y;
                    acc[i][2] += p * v0.z; acc[i][3] += p * v0.w;
                    acc[i][4] += p * v1.x; acc[i][5] += p * v1.y;
                    acc[i][6] += p * v1.z; acc[i][7] += p * v1.w;
                }
            }
        }
        __syncthreads();
    }

    // epilogue: normalize and store to [B, T, H*DH]
    const int b = bh / NH, h = bh % NH;
#pragma unroll
    for (int i = 0; i < 4; i++) {
        int r = q0 + ty * 4 + i;
        float li = 1.f / l_s[ty * 4 + i];
        float* op = Og + ((size_t)(b * T_SEQ + r)) * DMODEL + h * DHEAD + tx * 8;
        float4 o0, o1;
        o0.x = acc[i][0] * li; o0.y = acc[i][1] * li;
        o0.z = acc[i][2] * li; o0.w = acc[i][3] * li;
        o1.x = acc[i][4] * li; o1.y = acc[i][5] * li;
        o1.z = acc[i][6] * li; o1.w = acc[i][7] * li;
        *(float4*)op = o0;
        *(float4*)(op + 4) = o1;
    }
}

// ---------------- launch ----------------
extern "C" void kernel_launch(void* const* d_in, const int* in_sizes, int n_in,
                              void* d_out, int out_size)
{
    const float* x       = (const float*)d_in[0];
    const float* Wq_sem  = (const float*)d_in[1];
    const float* Wk_sem  = (const float*)d_in[2];
    const float* Wq_geo  = (const float*)d_in[3];
    const float* Wk_geo  = (const float*)d_in[4];
    const float* Wv      = (const float*)d_in[5];
    const float* Wo      = (const float*)d_in[6];
    const float* gate    = (const float*)d_in[7];
    const int*   pos_off = (const int*)d_in[8];
    float* out = (float*)d_out;

    float *qcat, *kcat, *v, *obuf;
    cudaGetSymbolAddress((void**)&qcat, g_Qcat);
    cudaGetSymbolAddress((void**)&kcat, g_Kcat);
    cudaGetSymbolAddress((void**)&v,    g_V);
    cudaGetSymbolAddress((void**)&obuf, g_O);

    const int M = BATCH * T_SEQ;   // 4096
    dim3 blk(256);

    // projections (writes head-split; sem -> dims [0,64), geo -> [64,128))
    gemm_kernel<<<dim3(1024 / 64, M / 64), blk>>>(x, Wq_sem, qcat, 1024, DMODEL, 64, 128, 0);
    gemm_kernel<<<dim3(1024 / 64, M / 64), blk>>>(x, Wq_geo, qcat, 1024, DMODEL, 64, 128, 64);
    gemm_kernel<<<dim3(1024 / 64, M / 64), blk>>>(x, Wk_sem, kcat, 1024, DMODEL, 64, 128, 0);
    gemm_kernel<<<dim3(1024 / 64, M / 64), blk>>>(x, Wk_geo, kcat, 1024, DMODEL, 64, 128, 64);
    gemm_kernel<<<dim3(2048 / 64, M / 64), blk>>>(x, Wv,     v,    2048, DMODEL, 128, 128, 0);

    // rope + gate folding
    rope_gate_kernel<<<BATCH * NH * T_SEQ / 4, 128>>>(qcat, kcat, gate, pos_off);

    // flash attention
    cudaFuncSetAttribute(flash_kernel, cudaFuncAttributeMaxDynamicSharedMemorySize,
                         SMEM_FLASH);
    flash_kernel<<<dim3(T_SEQ / BM, BATCH * NH), blk, SMEM_FLASH>>>(qcat, kcat, v, obuf);

    // output projection
    gemm_kernel<<<dim3(2048 / 64, M / 64), blk>>>(obuf, Wo, out, 2048, DMODEL, 2048, 2048, 0);
}

// round 3
// speedup vs baseline: 1.6178x; 1.6178x over previous
#include <cuda_runtime.h>
#include <math.h>
#include <stdint.h>

#define T_SEQ  2048
#define BATCH  2
#define DMODEL 2048
#define NH     16
#define DHEAD  128
#define DCAT   128

// ---------------- scratch (device globals: allocation-free) ----------------
__device__ float g_Qcat[(size_t)BATCH * NH * T_SEQ * DCAT];
__device__ float g_Kcat[(size_t)BATCH * NH * T_SEQ * DCAT];
__device__ float g_V  [(size_t)BATCH * NH * T_SEQ * DHEAD];
__device__ float g_O  [(size_t)BATCH * T_SEQ * DMODEL];
__device__ float g_WT [4u * 2048u * 1024u + 2u * 2048u * 2048u]; // transposed weights

// ---------------- helpers ----------------
__device__ __forceinline__ uint32_t smem_u32(const void* p) {
    uint32_t a;
    asm("{ .reg .u64 t; cvta.to.shared.u64 t, %1; cvt.u32.u64 %0, t; }" : "=r"(a) : "l"(p));
    return a;
}
__device__ __forceinline__ void cp16(uint32_t dst, const void* src) {
    asm volatile("cp.async.cg.shared.global [%0], [%1], 16;" :: "r"(dst), "l"(src) : "memory");
}
__device__ __forceinline__ uint32_t f2tf32(float f) {
    uint32_t r;
    asm("cvt.rna.tf32.f32 %0, %1;" : "=r"(r) : "f"(f));
    return r;
}
__device__ __forceinline__ void mma_tf32(float c[4], const uint32_t a[4], const uint32_t b[2]) {
    asm volatile(
        "mma.sync.aligned.m16n8k8.row.col.f32.tf32.tf32.f32 "
        "{%0,%1,%2,%3}, {%4,%5,%6,%7}, {%8,%9}, {%0,%1,%2,%3};"
        : "+f"(c[0]), "+f"(c[1]), "+f"(c[2]), "+f"(c[3])
        : "r"(a[0]), "r"(a[1]), "r"(a[2]), "r"(a[3]), "r"(b[0]), "r"(b[1]));
}

// ---------------- weight transpose: WT[n][k] = W[k][n], K=2048 ----------------
__global__ void transpose_kernel(const float* __restrict__ W, float* __restrict__ WT, int N)
{
    __shared__ float ts[32][33];
    int n0 = blockIdx.x * 32, k0 = blockIdx.y * 32;
    int x = threadIdx.x, y = threadIdx.y;  // 32 x 8
#pragma unroll
    for (int i = 0; i < 4; i++)
        ts[y + 8 * i][x] = W[(size_t)(k0 + y + 8 * i) * N + n0 + x];
    __syncthreads();
#pragma unroll
    for (int i = 0; i < 4; i++)
        WT[(size_t)(n0 + y + 8 * i) * 2048 + k0 + x] = ts[x][y + 8 * i];
}

// ---------------- tf32 HMMA GEMM: C = A(4096x2048) @ W, head-split epilogue --------
// CTA tile 128x128, k-chunk 32, 3-stage cp.async pipeline.
// smem stage: A 128 rows x 36 floats (pad), B 128 rows x 36 floats.
#define STG_FLT  9216            // floats per stage (A 4608 + B 4608)
#define STG_B    36864           // bytes per stage
#define GEMM_SMEM (3 * STG_B)    // 110592 B

__global__ __launch_bounds__(256, 1)
void gemm_mma(const float* __restrict__ A, const float* __restrict__ BT,
              float* __restrict__ out, int N, int hd, int ostride, int dstart)
{
    extern __shared__ float sm[];
    const uint32_t sbase = smem_u32(sm);

    const int tid  = threadIdx.x;
    const int wid  = tid >> 5;
    const int lane = tid & 31;
    const int wm = wid & 1;        // m-half (64 rows)
    const int wn = wid >> 1;       // n-quarter (32 cols)
    const int g  = lane >> 2;      // group id
    const int tg = lane & 3;       // thread in group

    const int bm = blockIdx.y * 128;
    const int bn = blockIdx.x * 128;

    const float* Ab = A  + (size_t)bm * 2048;
    const float* Bb = BT + (size_t)bn * 2048;

    auto load_tile = [&](int kt) {
        int s = kt % 3;
        uint32_t aB = sbase + s * STG_B;
        uint32_t bB = aB + 18432;
        int k0 = kt * 32;
#pragma unroll
        for (int j = 0; j < 4; j++) {
            int c = tid + 256 * j;
            int row = c >> 3, k4 = c & 7;
            cp16(aB + row * 144 + k4 * 16, Ab + (size_t)row * 2048 + k0 + k4 * 4);
        }
#pragma unroll
        for (int j = 0; j < 4; j++) {
            int c = tid + 256 * j;
            int row = c >> 3, k4 = c & 7;
            cp16(bB + row * 144 + k4 * 16, Bb + (size_t)row * 2048 + k0 + k4 * 4);
        }
    };

    float c[4][4][4];
#pragma unroll
    for (int mt = 0; mt < 4; mt++)
#pragma unroll
        for (int nt = 0; nt < 4; nt++)
#pragma unroll
            for (int i = 0; i < 4; i++) c[mt][nt][i] = 0.f;

    load_tile(0); asm volatile("cp.async.commit_group;" ::: "memory");
    load_tile(1); asm volatile("cp.async.commit_group;" ::: "memory");

    for (int it = 0; it < 64; it++) {
        asm volatile("cp.async.wait_group 1;" ::: "memory");
        __syncthreads();

        const float* As = sm + (it % 3) * STG_FLT;
        const float* Bs = As + 4608;

#pragma unroll
        for (int ks = 0; ks < 4; ks++) {
            uint32_t af[4][4], bf[4][2];
#pragma unroll
            for (int mt = 0; mt < 4; mt++) {
                const float* ap = As + (wm * 64 + mt * 16 + g) * 36 + ks * 8 + tg;
                af[mt][0] = f2tf32(ap[0]);
                af[mt][1] = f2tf32(ap[288]);   // +8 rows
                af[mt][2] = f2tf32(ap[4]);
                af[mt][3] = f2tf32(ap[292]);
            }
#pragma unroll
            for (int nt = 0; nt < 4; nt++) {
                const float* bp = Bs + (wn * 32 + nt * 8 + g) * 36 + ks * 8 + tg;
                bf[nt][0] = f2tf32(bp[0]);
                bf[nt][1] = f2tf32(bp[4]);
            }
#pragma unroll
            for (int mt = 0; mt < 4; mt++)
#pragma unroll
                for (int nt = 0; nt < 4; nt++)
                    mma_tf32(c[mt][nt], af[mt], bf[nt]);
        }

        int nt2 = it + 2;
        if (nt2 < 64) {
            __syncthreads();          // compute done before overwriting stage (it+2)%3
            load_tile(nt2);
        }
        asm volatile("cp.async.commit_group;" ::: "memory");
    }

    // epilogue: head-split store straight from fragments
    const int nheads = N / hd;
#pragma unroll
    for (int mt = 0; mt < 4; mt++) {
        int m0 = bm + wm * 64 + mt * 16 + g;
        int m1 = m0 + 8;
        int b0 = m0 >> 11, t0 = m0 & 2047;
        int b1 = m1 >> 11, t1 = m1 & 2047;
#pragma unroll
        for (int nt = 0; nt < 4; nt++) {
            int col = bn + wn * 32 + nt * 8 + tg * 2;
            int h = col / hd, d = col - h * hd;
            size_t i0 = (((size_t)b0 * nheads + h) * T_SEQ + t0) * (size_t)ostride + dstart + d;
            size_t i1 = (((size_t)b1 * nheads + h) * T_SEQ + t1) * (size_t)ostride + dstart + d;
            float2 v0 = make_float2(c[mt][nt][0], c[mt][nt][1]);
            float2 v1 = make_float2(c[mt][nt][2], c[mt][nt][3]);
            *(float2*)&out[i0] = v0;
            *(float2*)&out[i1] = v1;
        }
    }
}

// ---------------- RoPE + gate folding ----------------
__global__ void rope_gate_kernel(float* __restrict__ Qcat, float* __restrict__ Kcat,
                                 const float* __restrict__ gate_logit,
                                 const int* __restrict__ pos_off)
{
    int row  = blockIdx.x * 4 + (threadIdx.x >> 5);
    int lane = threadIdx.x & 31;

    int t = row % T_SEQ;
    int h = (row / T_SEQ) % NH;

    float g = 1.f / (1.f + expf(-gate_logit[h]));
    float qs_scale = 2.f * g * 0.125f;
    float qg_scale = (2.f - 2.f * g) * 0.125f;

    float freq = powf(10000.f, -(float)lane / 32.f);
    float ang  = (float)(t + pos_off[0]) * freq;
    float c = cosf(ang), s = sinf(ang);

    float* qp = Qcat + (size_t)row * DCAT;
    float* kp = Kcat + (size_t)row * DCAT;

    qp[lane]      *= qs_scale;
    qp[lane + 32] *= qs_scale;

    float x1 = qp[64 + lane], x2 = qp[96 + lane];
    qp[64 + lane] = (x1 * c - x2 * s) * qg_scale;
    qp[96 + lane] = (x2 * c + x1 * s) * qg_scale;

    float k1 = kp[64 + lane], k2 = kp[96 + lane];
    kp[64 + lane] = k1 * c - k2 * s;
    kp[96 + lane] = k2 * c + k1 * s;
}

// ---------------- flash attention (fp32, online softmax, causal) ----------------
#define BM 64
#define BN 64
#define SMEM_FLASH ((2 * 64 * 128 + 64 * 68 + 3 * 64) * 4)

__global__ __launch_bounds__(256)
void flash_kernel(const float* __restrict__ Q, const float* __restrict__ Kc,
                  const float* __restrict__ V, float* __restrict__ Og)
{
    extern __shared__ float sm[];
    float* Qs     = sm;
    float* Ks     = sm + 64 * 128;
    float* Ss     = sm + 2 * 64 * 128;
    float* m_s    = Ss + 64 * 68;
    float* l_s    = m_s + 64;
    float* corr_s = l_s + 64;

    const int qi = blockIdx.x;
    const int bh = blockIdx.y;
    const int q0 = qi * BM;

    const float* Qb = Q  + ((size_t)bh * T_SEQ + q0) * DCAT;
    const float* Kb = Kc + (size_t)bh * T_SEQ * DCAT;
    const float* Vb = V  + (size_t)bh * T_SEQ * DHEAD;

    const int tid = threadIdx.x;
    const int tx = tid % 16;
    const int ty = tid / 16;

    for (int i = tid; i < 64 * 128 / 4; i += 256)
        ((float4*)Qs)[i] = ((const float4*)Qb)[i];
    if (tid < 64) { m_s[tid] = -1e30f; l_s[tid] = 0.f; }

    float acc[4][8];
#pragma unroll
    for (int i = 0; i < 4; i++)
#pragma unroll
        for (int j = 0; j < 8; j++) acc[i][j] = 0.f;

    __syncthreads();

    for (int kt = 0; kt <= qi; kt++) {
        const int k0 = kt * BN;

        for (int i = tid; i < 64 * 128 / 4; i += 256)
            ((float4*)Ks)[i] = ((const float4*)(Kb + (size_t)k0 * DCAT))[i];
        __syncthreads();

        float s4[4][4] = {};
#pragma unroll 4
        for (int k = 0; k < DCAT; k += 4) {
            float4 a[4], b[4];
#pragma unroll
            for (int i = 0; i < 4; i++) a[i] = *(float4*)&Qs[(ty * 4 + i) * 128 + k];
#pragma unroll
            for (int j = 0; j < 4; j++) b[j] = *(float4*)&Ks[(tx * 4 + j) * 128 + k];
#pragma unroll
            for (int i = 0; i < 4; i++)
#pragma unroll
                for (int j = 0; j < 4; j++)
                    s4[i][j] += a[i].x * b[j].x + a[i].y * b[j].y +
                                a[i].z * b[j].z + a[i].w * b[j].w;
        }
        const bool diag = (kt == qi);
#pragma unroll
        for (int i = 0; i < 4; i++) {
            int r = ty * 4 + i;
#pragma unroll
            for (int j = 0; j < 4; j++) {
                int col = tx * 4 + j;
                float v = s4[i][j];
                if (diag && col > r) v = -1e30f;
                Ss[r * 68 + col] = v;
            }
        }
        __syncthreads();

        // online softmax: 4 threads per row
        {
            int r = tid >> 2, sub = tid & 3;
            float mold = m_s[r];
            float mx = mold;
#pragma unroll
            for (int j = 0; j < 16; j++) mx = fmaxf(mx, Ss[r * 68 + sub * 16 + j]);
            mx = fmaxf(mx, __shfl_xor_sync(0xffffffffu, mx, 1));
            mx = fmaxf(mx, __shfl_xor_sync(0xffffffffu, mx, 2));
            float sum = 0.f;
#pragma unroll
            for (int j = 0; j < 16; j++) {
                float p = __expf(Ss[r * 68 + sub * 16 + j] - mx);
                Ss[r * 68 + sub * 16 + j] = p;
                sum += p;
            }
            sum += __shfl_xor_sync(0xffffffffu, sum, 1);
            sum += __shfl_xor_sync(0xffffffffu, sum, 2);
            if (sub == 0) {
                float corr = __expf(mold - mx);
                l_s[r] = l_s[r] * corr + sum;
                m_s[r] = mx;
                corr_s[r] = corr;
            }
        }
        __syncthreads();

        float cr[4];
#pragma unroll
        for (int i = 0; i < 4; i++) cr[i] = corr_s[ty * 4 + i];
#pragma unroll
        for (int i = 0; i < 4; i++)
#pragma unroll
            for (int j = 0; j < 8; j++) acc[i][j] *= cr[i];

        for (int i = tid; i < 64 * 128 / 4; i += 256)
            ((float4*)Ks)[i] = ((const float4*)(Vb + (size_t)k0 * DHEAD))[i];
        __syncthreads();

#pragma unroll 2
        for (int k = 0; k < BN; k += 4) {
            float pr[4][4];
#pragma unroll
            for (int i = 0; i < 4; i++) {
                float4 p4 = *(float4*)&Ss[(ty * 4 + i) * 68 + k];
                pr[i][0] = p4.x; pr[i][1] = p4.y; pr[i][2] = p4.z; pr[i][3] = p4.w;
            }
#pragma unroll
            for (int kk = 0; kk < 4; kk++) {
                float4 v0 = *(float4*)&Ks[(k + kk) * 128 + tx * 8];
                float4 v1 = *(float4*)&Ks[(k + kk) * 128 + tx * 8 + 4];
#pragma unroll
                for (int i = 0; i < 4; i++) {
                    float p = pr[i][kk];
                    acc[i][0] += p * v0.x; acc[i][1] += p * v0.y;
                    acc[i][2] += p * v0.z; acc[i][3] += p * v0.w;
                    acc[i][4] += p * v1.x; acc[i][5] += p * v1.y;
                    acc[i][6] += p * v1.z; acc[i][7] += p * v1.w;
                }
            }
        }
        __syncthreads();
    }

    const int b = bh / NH, h = bh % NH;
#pragma unroll
    for (int i = 0; i < 4; i++) {
        int r = q0 + ty * 4 + i;
        float li = 1.f / l_s[ty * 4 + i];
        float* op = Og + ((size_t)(b * T_SEQ + r)) * DMODEL + h * DHEAD + tx * 8;
        float4 o0, o1;
        o0.x = acc[i][0] * li; o0.y = acc[i][1] * li;
        o0.z = acc[i][2] * li; o0.w = acc[i][3] * li;
        o1.x = acc[i][4] * li; o1.y = acc[i][5] * li;
        o1.z = acc[i][6] * li; o1.w = acc[i][7] * li;
        *(float4*)op = o0;
        *(float4*)(op + 4) = o1;
    }
}

// ---------------- launch ----------------
extern "C" void kernel_launch(void* const* d_in, const int* in_sizes, int n_in,
                              void* d_out, int out_size)
{
    const float* x       = (const float*)d_in[0];
    const float* Wq_sem  = (const float*)d_in[1];
    const float* Wk_sem  = (const float*)d_in[2];
    const float* Wq_geo  = (const float*)d_in[3];
    const float* Wk_geo  = (const float*)d_in[4];
    const float* Wv      = (const float*)d_in[5];
    const float* Wo      = (const float*)d_in[6];
    const float* gate    = (const float*)d_in[7];
    const int*   pos_off = (const int*)d_in[8];
    float* out = (float*)d_out;

    float *qcat, *kcat, *v, *obuf, *wt;
    cudaGetSymbolAddress((void**)&qcat, g_Qcat);
    cudaGetSymbolAddress((void**)&kcat, g_Kcat);
    cudaGetSymbolAddress((void**)&v,    g_V);
    cudaGetSymbolAddress((void**)&obuf, g_O);
    cudaGetSymbolAddress((void**)&wt,   g_WT);

    const size_t SZ_S = 2048u * 1024u;
    float* wtQs = wt;
    float* wtKs = wt + SZ_S;
    float* wtQg = wt + 2 * SZ_S;
    float* wtKg = wt + 3 * SZ_S;
    float* wtV  = wt + 4 * SZ_S;
    float* wtO  = wt + 4 * SZ_S + 2048u * 2048u;

    dim3 tb(32, 8);
    transpose_kernel<<<dim3(1024 / 32, 64), tb>>>(Wq_sem, wtQs, 1024);
    transpose_kernel<<<dim3(1024 / 32, 64), tb>>>(Wk_sem, wtKs, 1024);
    transpose_kernel<<<dim3(1024 / 32, 64), tb>>>(Wq_geo, wtQg, 1024);
    transpose_kernel<<<dim3(1024 / 32, 64), tb>>>(Wk_geo, wtKg, 1024);
    transpose_kernel<<<dim3(2048 / 32, 64), tb>>>(Wv,     wtV,  2048);
    transpose_kernel<<<dim3(2048 / 32, 64), tb>>>(Wo,     wtO,  2048);

    cudaFuncSetAttribute(gemm_mma, cudaFuncAttributeMaxDynamicSharedMemorySize, GEMM_SMEM);

    // projections: tf32 HMMA GEMMs with head-split epilogues
    gemm_mma<<<dim3(1024 / 128, 32), 256, GEMM_SMEM>>>(x, wtQs, qcat, 1024, 64, 128, 0);
    gemm_mma<<<dim3(1024 / 128, 32), 256, GEMM_SMEM>>>(x, wtQg, qcat, 1024, 64, 128, 64);
    gemm_mma<<<dim3(1024 / 128, 32), 256, GEMM_SMEM>>>(x, wtKs, kcat, 1024, 64, 128, 0);
    gemm_mma<<<dim3(1024 / 128, 32), 256, GEMM_SMEM>>>(x, wtKg, kcat, 1024, 64, 128, 64);
    gemm_mma<<<dim3(2048 / 128, 32), 256, GEMM_SMEM>>>(x, wtV,  v,    2048, 128, 128, 0);

    rope_gate_kernel<<<BATCH * NH * T_SEQ / 4, 128>>>(qcat, kcat, gate, pos_off);

    cudaFuncSetAttribute(flash_kernel, cudaFuncAttributeMaxDynamicSharedMemorySize, SMEM_FLASH);
    flash_kernel<<<dim3(T_SEQ / BM, BATCH * NH), 256, SMEM_FLASH>>>(qcat, kcat, v, obuf);

    gemm_mma<<<dim3(2048 / 128, 32), 256, GEMM_SMEM>>>(obuf, wtO, out, 2048, 2048, 2048, 0);
}

// round 4
// speedup vs baseline: 3.6424x; 2.2515x over previous
#include <cuda_runtime.h>
#include <math.h>
#include <stdint.h>

#define T_SEQ  2048
#define BATCH  2
#define DMODEL 2048
#define NH     16
#define DHEAD  128
#define DCAT   128

// ---------------- scratch (device globals: allocation-free) ----------------
__device__ float g_Qcat[(size_t)BATCH * NH * T_SEQ * DCAT];
__device__ float g_Kcat[(size_t)BATCH * NH * T_SEQ * DCAT];
__device__ float g_Vt [(size_t)BATCH * NH * DHEAD * T_SEQ];   // V transposed: [bh][d][t]
__device__ float g_O  [(size_t)BATCH * T_SEQ * DMODEL];
__device__ float g_WT [4u * 2048u * 1024u + 2u * 2048u * 2048u];

// ---------------- helpers ----------------
__device__ __forceinline__ uint32_t smem_u32(const void* p) {
    uint32_t a;
    asm("{ .reg .u64 t; cvta.to.shared.u64 t, %1; cvt.u32.u64 %0, t; }" : "=r"(a) : "l"(p));
    return a;
}
__device__ __forceinline__ void cp16(uint32_t dst, const void* src) {
    asm volatile("cp.async.cg.shared.global [%0], [%1], 16;" :: "r"(dst), "l"(src) : "memory");
}
__device__ __forceinline__ uint32_t f2tf32(float f) {
    uint32_t r;
    asm("cvt.rna.tf32.f32 %0, %1;" : "=r"(r) : "f"(f));
    return r;
}
__device__ __forceinline__ void mma_tf32(float c[4], const uint32_t a[4], const uint32_t b[2]) {
    asm volatile(
        "mma.sync.aligned.m16n8k8.row.col.f32.tf32.tf32.f32 "
        "{%0,%1,%2,%3}, {%4,%5,%6,%7}, {%8,%9}, {%0,%1,%2,%3};"
        : "+f"(c[0]), "+f"(c[1]), "+f"(c[2]), "+f"(c[3])
        : "r"(a[0]), "r"(a[1]), "r"(a[2]), "r"(a[3]), "r"(b[0]), "r"(b[1]));
}

// ---------------- weight transpose: WT[n][k] = W[k][n], K=2048 ----------------
__global__ void transpose_kernel(const float* __restrict__ W, float* __restrict__ WT, int N)
{
    __shared__ float ts[32][33];
    int n0 = blockIdx.x * 32, k0 = blockIdx.y * 32;
    int x = threadIdx.x, y = threadIdx.y;
#pragma unroll
    for (int i = 0; i < 4; i++)
        ts[y + 8 * i][x] = W[(size_t)(k0 + y + 8 * i) * N + n0 + x];
    __syncthreads();
#pragma unroll
    for (int i = 0; i < 4; i++)
        WT[(size_t)(n0 + y + 8 * i) * 2048 + k0 + x] = ts[x][y + 8 * i];
}

// ---------------- tf32 HMMA GEMM (128x128 tile, 3-stage cp.async) ----------------
#define STG_FLT  9216
#define STG_B    36864
#define GEMM_SMEM (3 * STG_B)

__global__ __launch_bounds__(256, 1)
void gemm_mma(const float* __restrict__ A, const float* __restrict__ BT,
              float* __restrict__ out, int N, int hd, int ostride, int dstart,
              int vtrans)
{
    extern __shared__ float sm[];
    const uint32_t sbase = smem_u32(sm);

    const int tid  = threadIdx.x;
    const int wid  = tid >> 5;
    const int lane = tid & 31;
    const int wm = wid & 1;
    const int wn = wid >> 1;
    const int g  = lane >> 2;
    const int tg = lane & 3;

    const int bm = blockIdx.y * 128;
    const int bn = blockIdx.x * 128;

    const float* Ab = A  + (size_t)bm * 2048;
    const float* Bb = BT + (size_t)bn * 2048;

    auto load_tile = [&](int kt) {
        int s = kt % 3;
        uint32_t aB = sbase + s * STG_B;
        uint32_t bB = aB + 18432;
        int k0 = kt * 32;
#pragma unroll
        for (int j = 0; j < 4; j++) {
            int c = tid + 256 * j;
            int row = c >> 3, k4 = c & 7;
            cp16(aB + row * 144 + k4 * 16, Ab + (size_t)row * 2048 + k0 + k4 * 4);
        }
#pragma unroll
        for (int j = 0; j < 4; j++) {
            int c = tid + 256 * j;
            int row = c >> 3, k4 = c & 7;
            cp16(bB + row * 144 + k4 * 16, Bb + (size_t)row * 2048 + k0 + k4 * 4);
        }
    };

    float c[4][4][4];
#pragma unroll
    for (int mt = 0; mt < 4; mt++)
#pragma unroll
        for (int nt = 0; nt < 4; nt++)
#pragma unroll
            for (int i = 0; i < 4; i++) c[mt][nt][i] = 0.f;

    load_tile(0); asm volatile("cp.async.commit_group;" ::: "memory");
    load_tile(1); asm volatile("cp.async.commit_group;" ::: "memory");

    for (int it = 0; it < 64; it++) {
        asm volatile("cp.async.wait_group 1;" ::: "memory");
        __syncthreads();

        const float* As = sm + (it % 3) * STG_FLT;
        const float* Bs = As + 4608;

#pragma unroll
        for (int ks = 0; ks < 4; ks++) {
            uint32_t af[4][4], bf[4][2];
#pragma unroll
            for (int mt = 0; mt < 4; mt++) {
                const float* ap = As + (wm * 64 + mt * 16 + g) * 36 + ks * 8 + tg;
                af[mt][0] = f2tf32(ap[0]);
                af[mt][1] = f2tf32(ap[288]);
                af[mt][2] = f2tf32(ap[4]);
                af[mt][3] = f2tf32(ap[292]);
            }
#pragma unroll
            for (int nt = 0; nt < 4; nt++) {
                const float* bp = Bs + (wn * 32 + nt * 8 + g) * 36 + ks * 8 + tg;
                bf[nt][0] = f2tf32(bp[0]);
                bf[nt][1] = f2tf32(bp[4]);
            }
#pragma unroll
            for (int mt = 0; mt < 4; mt++)
#pragma unroll
                for (int nt = 0; nt < 4; nt++)
                    mma_tf32(c[mt][nt], af[mt], bf[nt]);
        }

        int nt2 = it + 2;
        if (nt2 < 64) {
            __syncthreads();
            load_tile(nt2);
        }
        asm volatile("cp.async.commit_group;" ::: "memory");
    }

    const int nheads = N / hd;
#pragma unroll
    for (int mt = 0; mt < 4; mt++) {
        int m0 = bm + wm * 64 + mt * 16 + g;
        int m1 = m0 + 8;
        int b0 = m0 >> 11, t0 = m0 & 2047;
        int b1 = m1 >> 11, t1 = m1 & 2047;
#pragma unroll
        for (int nt = 0; nt < 4; nt++) {
            int col = bn + wn * 32 + nt * 8 + tg * 2;
            if (vtrans) {
                // out[((b*16 + h)*128 + d) * 2048 + t]
                int h = col >> 7, d = col & 127;
                size_t base0 = ((size_t)(b0 * NH + h) * 128 + d) * 2048;
                size_t base1 = ((size_t)(b1 * NH + h) * 128 + d) * 2048;
                out[base0 + t0]        = c[mt][nt][0];
                out[base0 + 2048 + t0] = c[mt][nt][1];
                out[base1 + t1]        = c[mt][nt][2];
                out[base1 + 2048 + t1] = c[mt][nt][3];
            } else {
                int h = col / hd, d = col - h * hd;
                size_t i0 = (((size_t)b0 * nheads + h) * T_SEQ + t0) * (size_t)ostride + dstart + d;
                size_t i1 = (((size_t)b1 * nheads + h) * T_SEQ + t1) * (size_t)ostride + dstart + d;
                *(float2*)&out[i0] = make_float2(c[mt][nt][0], c[mt][nt][1]);
                *(float2*)&out[i1] = make_float2(c[mt][nt][2], c[mt][nt][3]);
            }
        }
    }
}

// ---------------- RoPE + gate folding ----------------
__global__ void rope_gate_kernel(float* __restrict__ Qcat, float* __restrict__ Kcat,
                                 const float* __restrict__ gate_logit,
                                 const int* __restrict__ pos_off)
{
    int row  = blockIdx.x * 4 + (threadIdx.x >> 5);
    int lane = threadIdx.x & 31;

    int t = row % T_SEQ;
    int h = (row / T_SEQ) % NH;

    float g = 1.f / (1.f + expf(-gate_logit[h]));
    float qs_scale = 2.f * g * 0.125f;
    float qg_scale = (2.f - 2.f * g) * 0.125f;

    float freq = powf(10000.f, -(float)lane / 32.f);
    float ang  = (float)(t + pos_off[0]) * freq;
    float c = cosf(ang), s = sinf(ang);

    float* qp = Qcat + (size_t)row * DCAT;
    float* kp = Kcat + (size_t)row * DCAT;

    qp[lane]      *= qs_scale;
    qp[lane + 32] *= qs_scale;

    float x1 = qp[64 + lane], x2 = qp[96 + lane];
    qp[64 + lane] = (x1 * c - x2 * s) * qg_scale;
    qp[96 + lane] = (x2 * c + x1 * s) * qg_scale;

    float k1 = kp[64 + lane], k2 = kp[96 + lane];
    kp[64 + lane] = k1 * c - k2 * s;
    kp[96 + lane] = k2 * c + k1 * s;
}

// ---------------- mma flash attention ----------------
// BM=128 (8 warps x 16 rows), BN=64. smem (floats):
//   Qs [128][132] @0, Ks [64][132] @16896, Vs [128][68] @25344 (d-major),
//   Ss [128][68] @34048, m @42752, l @42880, corr @43008; total 43136
#define FL_QS 0
#define FL_KS 16896
#define FL_VS 25344
#define FL_SS 34048
#define FL_M  42752
#define SMEM_FLASH (43136 * 4)

__global__ __launch_bounds__(256, 1)
void flash_mma(const float* __restrict__ Q, const float* __restrict__ Kc,
               const float* __restrict__ Vt, float* __restrict__ Og)
{
    extern __shared__ float sm[];
    const uint32_t sb = smem_u32(sm);
    float* Qs     = sm + FL_QS;
    float* Ks     = sm + FL_KS;
    float* Vs     = sm + FL_VS;
    float* Ss     = sm + FL_SS;
    float* m_s    = sm + FL_M;
    float* l_s    = m_s + 128;
    float* corr_s = l_s + 128;

    const int qi = blockIdx.x;
    const int bh = blockIdx.y;
    const int q0 = qi * 128;

    const int tid  = threadIdx.x;
    const int wid  = tid >> 5;
    const int lane = tid & 31;
    const int g  = lane >> 2;
    const int tg = lane & 3;
    const int m0 = wid * 16;

    const float* Qb = Q  + ((size_t)bh * T_SEQ + q0) * DCAT;
    const float* Kb = Kc + (size_t)bh * T_SEQ * DCAT;
    const float* Vb = Vt + (size_t)bh * DHEAD * T_SEQ;

    auto loadK = [&](int kt) {
        const float* src = Kb + (size_t)kt * 64 * DCAT;
#pragma unroll
        for (int j = 0; j < 8; j++) {
            int i = tid + 256 * j;
            int r = i >> 5, c4 = i & 31;
            cp16(sb + (FL_KS + r * 132 + c4 * 4) * 4, src + r * DCAT + c4 * 4);
        }
    };
    auto loadV = [&](int kt) {
#pragma unroll
        for (int j = 0; j < 8; j++) {
            int i = tid + 256 * j;
            int d = i >> 4, c4 = i & 15;
            cp16(sb + (FL_VS + d * 68 + c4 * 4) * 4, Vb + (size_t)d * T_SEQ + kt * 64 + c4 * 4);
        }
    };

    // prologue: Q + K0 in group 0, V0 in group 1
#pragma unroll
    for (int j = 0; j < 16; j++) {
        int i = tid + 256 * j;
        int r = i >> 5, c4 = i & 31;
        cp16(sb + (FL_QS + r * 132 + c4 * 4) * 4, Qb + (size_t)r * DCAT + c4 * 4);
    }
    loadK(0);
    asm volatile("cp.async.commit_group;" ::: "memory");
    loadV(0);
    asm volatile("cp.async.commit_group;" ::: "memory");

    if (tid < 128) { m_s[tid] = -1e30f; l_s[tid] = 0.f; }

    float of[16][4];
#pragma unroll
    for (int nt = 0; nt < 16; nt++)
#pragma unroll
        for (int i = 0; i < 4; i++) of[nt][i] = 0.f;

    const int nkt = 2 * (qi + 1);

    for (int kt = 0; kt < nkt; kt++) {
        const int k0 = kt * 64;

        asm volatile("cp.async.wait_group 1;" ::: "memory");   // Q+K(kt) ready
        __syncthreads();

        // ---- S = Q K^T, 3-term split tf32 ----
        float sc[8][4];
#pragma unroll
        for (int nt = 0; nt < 8; nt++)
#pragma unroll
            for (int i = 0; i < 4; i++) sc[nt][i] = 0.f;

#pragma unroll
        for (int ks = 0; ks < 16; ks++) {
            const float* ap = Qs + (m0 + g) * 132 + ks * 8 + tg;
            float a0 = ap[0], a1 = ap[8 * 132], a2 = ap[4], a3 = ap[8 * 132 + 4];
            uint32_t ah[4] = {f2tf32(a0), f2tf32(a1), f2tf32(a2), f2tf32(a3)};
            uint32_t al[4] = {f2tf32(a0 - __uint_as_float(ah[0])),
                              f2tf32(a1 - __uint_as_float(ah[1])),
                              f2tf32(a2 - __uint_as_float(ah[2])),
                              f2tf32(a3 - __uint_as_float(ah[3]))};
#pragma unroll
            for (int nt = 0; nt < 8; nt++) {
                const float* bp = Ks + (nt * 8 + g) * 132 + ks * 8 + tg;
                float b0 = bp[0], b1 = bp[4];
                uint32_t bhh[2] = {f2tf32(b0), f2tf32(b1)};
                uint32_t bll[2] = {f2tf32(b0 - __uint_as_float(bhh[0])),
                                   f2tf32(b1 - __uint_as_float(bhh[1]))};
                mma_tf32(sc[nt], ah, bhh);
                mma_tf32(sc[nt], al, bhh);
                mma_tf32(sc[nt], ah, bll);
            }
        }

        // ---- mask + store S fragments to Ss ----
        const int gr1 = q0 + m0 + g, gr2 = gr1 + 8;
#pragma unroll
        for (int nt = 0; nt < 8; nt++) {
            int gc = k0 + nt * 8 + 2 * tg;
            float v0 = (gc     > gr1) ? -1e30f : sc[nt][0];
            float v1 = (gc + 1 > gr1) ? -1e30f : sc[nt][1];
            float v2 = (gc     > gr2) ? -1e30f : sc[nt][2];
            float v3 = (gc + 1 > gr2) ? -1e30f : sc[nt][3];
            *(float2*)&Ss[(m0 + g) * 68 + nt * 8 + 2 * tg]     = make_float2(v0, v1);
            *(float2*)&Ss[(m0 + g + 8) * 68 + nt * 8 + 2 * tg] = make_float2(v2, v3);
        }
        __syncthreads();

        // prefetch next K (Ks consumed)
        if (kt + 1 < nkt) loadK(kt + 1);
        asm volatile("cp.async.commit_group;" ::: "memory");

        // ---- online softmax: 2 threads per row ----
        {
            int r = tid >> 1, sub = tid & 1;
            float mold = m_s[r];
            float mx = mold;
            const float* sr = Ss + r * 68 + sub * 32;
#pragma unroll
            for (int j = 0; j < 32; j++) mx = fmaxf(mx, sr[j]);
            mx = fmaxf(mx, __shfl_xor_sync(0xffffffffu, mx, 1));
            float sum = 0.f;
            float* sw = Ss + r * 68 + sub * 32;
#pragma unroll
            for (int j = 0; j < 32; j++) {
                float p = __expf(sw[j] - mx);
                sw[j] = p;
                sum += p;
            }
            sum += __shfl_xor_sync(0xffffffffu, sum, 1);
            if (sub == 0) {
                float corr = __expf(mold - mx);
                l_s[r] = l_s[r] * corr + sum;
                m_s[r] = mx;
                corr_s[r] = corr;
            }
        }
        __syncthreads();

        // wait V(kt): if we just committed K(kt+1), allow 1 pending; else 0
        if (kt + 1 < nkt)
            asm volatile("cp.async.wait_group 1;" ::: "memory");
        else
            asm volatile("cp.async.wait_group 0;" ::: "memory");
        __syncthreads();

        // ---- rescale O, then O += P V (P split, V plain tf32) ----
        float c1 = corr_s[m0 + g], c2 = corr_s[m0 + g + 8];
#pragma unroll
        for (int nt = 0; nt < 16; nt++) {
            of[nt][0] *= c1; of[nt][1] *= c1;
            of[nt][2] *= c2; of[nt][3] *= c2;
        }

#pragma unroll
        for (int ks = 0; ks < 8; ks++) {
            const float* pp = Ss + (m0 + g) * 68 + ks * 8 + tg;
            float p0 = pp[0], p1 = pp[8 * 68], p2 = pp[4], p3 = pp[8 * 68 + 4];
            uint32_t ph[4] = {f2tf32(p0), f2tf32(p1), f2tf32(p2), f2tf32(p3)};
            uint32_t pl[4] = {f2tf32(p0 - __uint_as_float(ph[0])),
                              f2tf32(p1 - __uint_as_float(ph[1])),
                              f2tf32(p2 - __uint_as_float(ph[2])),
                              f2tf32(p3 - __uint_as_float(ph[3]))};
#pragma unroll
            for (int nt = 0; nt < 16; nt++) {
                const float* vp = Vs + (nt * 8 + g) * 68 + ks * 8 + tg;
                uint32_t bv[2] = {f2tf32(vp[0]), f2tf32(vp[4])};
                mma_tf32(of[nt], ph, bv);
                mma_tf32(of[nt], pl, bv);
            }
        }
        __syncthreads();

        // prefetch next V (Vs consumed)
        if (kt + 1 < nkt) {
            loadV(kt + 1);
            asm volatile("cp.async.commit_group;" ::: "memory");
        }
    }

    // ---- epilogue: normalize, store to [B, T, H*DH] ----
    const int b = bh >> 4, h = bh & 15;
    float il1 = 1.f / l_s[m0 + g];
    float il2 = 1.f / l_s[m0 + g + 8];
    int r1 = q0 + m0 + g, r2 = r1 + 8;
#pragma unroll
    for (int nt = 0; nt < 16; nt++) {
        int col = nt * 8 + 2 * tg;
        size_t i1 = ((size_t)(b * T_SEQ + r1)) * DMODEL + h * DHEAD + col;
        size_t i2 = ((size_t)(b * T_SEQ + r2)) * DMODEL + h * DHEAD + col;
        *(float2*)&Og[i1] = make_float2(of[nt][0] * il1, of[nt][1] * il1);
        *(float2*)&Og[i2] = make_float2(of[nt][2] * il2, of[nt][3] * il2);
    }
}

// ---------------- launch ----------------
extern "C" void kernel_launch(void* const* d_in, const int* in_sizes, int n_in,
                              void* d_out, int out_size)
{
    const float* x       = (const float*)d_in[0];
    const float* Wq_sem  = (const float*)d_in[1];
    const float* Wk_sem  = (const float*)d_in[2];
    const float* Wq_geo  = (const float*)d_in[3];
    const float* Wk_geo  = (const float*)d_in[4];
    const float* Wv      = (const float*)d_in[5];
    const float* Wo      = (const float*)d_in[6];
    const float* gate    = (const float*)d_in[7];
    const int*   pos_off = (const int*)d_in[8];
    float* out = (float*)d_out;

    float *qcat, *kcat, *vt, *obuf, *wt;
    cudaGetSymbolAddress((void**)&qcat, g_Qcat);
    cudaGetSymbolAddress((void**)&kcat, g_Kcat);
    cudaGetSymbolAddress((void**)&vt,   g_Vt);
    cudaGetSymbolAddress((void**)&obuf, g_O);
    cudaGetSymbolAddress((void**)&wt,   g_WT);

    const size_t SZ_S = 2048u * 1024u;
    float* wtQs = wt;
    float* wtKs = wt + SZ_S;
    float* wtQg = wt + 2 * SZ_S;
    float* wtKg = wt + 3 * SZ_S;
    float* wtV  = wt + 4 * SZ_S;
    float* wtO  = wt + 4 * SZ_S + 2048u * 2048u;

    dim3 tb(32, 8);
    transpose_kernel<<<dim3(1024 / 32, 64), tb>>>(Wq_sem, wtQs, 1024);
    transpose_kernel<<<dim3(1024 / 32, 64), tb>>>(Wk_sem, wtKs, 1024);
    transpose_kernel<<<dim3(1024 / 32, 64), tb>>>(Wq_geo, wtQg, 1024);
    transpose_kernel<<<dim3(1024 / 32, 64), tb>>>(Wk_geo, wtKg, 1024);
    transpose_kernel<<<dim3(2048 / 32, 64), tb>>>(Wv,     wtV,  2048);
    transpose_kernel<<<dim3(2048 / 32, 64), tb>>>(Wo,     wtO,  2048);

    cudaFuncSetAttribute(gemm_mma, cudaFuncAttributeMaxDynamicSharedMemorySize, GEMM_SMEM);

    gemm_mma<<<dim3(1024 / 128, 32), 256, GEMM_SMEM>>>(x, wtQs, qcat, 1024, 64, 128, 0, 0);
    gemm_mma<<<dim3(1024 / 128, 32), 256, GEMM_SMEM>>>(x, wtQg, qcat, 1024, 64, 128, 64, 0);
    gemm_mma<<<dim3(1024 / 128, 32), 256, GEMM_SMEM>>>(x, wtKs, kcat, 1024, 64, 128, 0, 0);
    gemm_mma<<<dim3(1024 / 128, 32), 256, GEMM_SMEM>>>(x, wtKg, kcat, 1024, 64, 128, 64, 0);
    gemm_mma<<<dim3(2048 / 128, 32), 256, GEMM_SMEM>>>(x, wtV,  vt,   2048, 128, 128, 0, 1);

    rope_gate_kernel<<<BATCH * NH * T_SEQ / 4, 128>>>(qcat, kcat, gate, pos_off);

    cudaFuncSetAttribute(flash_mma, cudaFuncAttributeMaxDynamicSharedMemorySize, SMEM_FLASH);
    flash_mma<<<dim3(T_SEQ / 128, BATCH * NH), 256, SMEM_FLASH>>>(qcat, kcat, vt, obuf);

    gemm_mma<<<dim3(2048 / 128, 32), 256, GEMM_SMEM>>>(obuf, wtO, out, 2048, 2048, 2048, 0, 0);
}

// round 5
// speedup vs baseline: 4.2380x; 1.1635x over previous
#include <cuda_runtime.h>
#include <math.h>
#include <stdint.h>

#define T_SEQ  2048
#define BATCH  2
#define DMODEL 2048
#define NH     16
#define DHEAD  128
#define DCAT   128

// ---------------- scratch (device globals: allocation-free) ----------------
__device__ float g_Qcat[(size_t)BATCH * NH * T_SEQ * DCAT];
__device__ float g_Kcat[(size_t)BATCH * NH * T_SEQ * DCAT];
__device__ float g_Vt [(size_t)BATCH * NH * DHEAD * T_SEQ];   // V transposed: [bh][d][t]
__device__ float g_O  [(size_t)BATCH * T_SEQ * DMODEL];
__device__ float g_WT [4u * 2048u * 1024u + 2u * 2048u * 2048u];
__device__ float g_Xr [(size_t)BATCH * T_SEQ * DMODEL];       // x pre-rounded to tf32

// ---------------- helpers ----------------
__device__ __forceinline__ uint32_t smem_u32(const void* p) {
    uint32_t a;
    asm("{ .reg .u64 t; cvta.to.shared.u64 t, %1; cvt.u32.u64 %0, t; }" : "=r"(a) : "l"(p));
    return a;
}
__device__ __forceinline__ void cp16(uint32_t dst, const void* src) {
    asm volatile("cp.async.cg.shared.global [%0], [%1], 16;" :: "r"(dst), "l"(src) : "memory");
}
__device__ __forceinline__ uint32_t f2tf32(float f) {
    uint32_t r;
    asm("cvt.rna.tf32.f32 %0, %1;" : "=r"(r) : "f"(f));
    return r;
}
__device__ __forceinline__ float f2tf32f(float f) { return __uint_as_float(f2tf32(f)); }
__device__ __forceinline__ void mma_tf32(float c[4], const uint32_t a[4], const uint32_t b[2]) {
    asm volatile(
        "mma.sync.aligned.m16n8k8.row.col.f32.tf32.tf32.f32 "
        "{%0,%1,%2,%3}, {%4,%5,%6,%7}, {%8,%9}, {%0,%1,%2,%3};"
        : "+f"(c[0]), "+f"(c[1]), "+f"(c[2]), "+f"(c[3])
        : "r"(a[0]), "r"(a[1]), "r"(a[2]), "r"(a[3]), "r"(b[0]), "r"(b[1]));
}

// ---------------- elementwise tf32 pre-round ----------------
__global__ void round_tf32_kernel(const float* __restrict__ in, float* __restrict__ out)
{
    int i = blockIdx.x * 256 + threadIdx.x;
    float4 v = ((const float4*)in)[i];
    v.x = f2tf32f(v.x); v.y = f2tf32f(v.y); v.z = f2tf32f(v.z); v.w = f2tf32f(v.w);
    ((float4*)out)[i] = v;
}

// ---------------- weight transpose + tf32 round: WT[n][k] = tf32(W[k][n]) ----------------
__global__ void transpose_kernel(const float* __restrict__ W, float* __restrict__ WT, int N)
{
    __shared__ float ts[32][33];
    int n0 = blockIdx.x * 32, k0 = blockIdx.y * 32;
    int x = threadIdx.x, y = threadIdx.y;
#pragma unroll
    for (int i = 0; i < 4; i++)
        ts[y + 8 * i][x] = W[(size_t)(k0 + y + 8 * i) * N + n0 + x];
    __syncthreads();
#pragma unroll
    for (int i = 0; i < 4; i++)
        WT[(size_t)(n0 + y + 8 * i) * 2048 + k0 + x] = f2tf32f(ts[x][y + 8 * i]);
}

// ---------------- tf32 HMMA GEMM (128x128 tile, 4-stage cp.async, no inner cvt) -------
// modes: 0 = fused QK projections (N=4096, out0=qcat, out1=kcat)
//        1 = V projection, transposed store (out0 = Vt[bh][d][t])
//        2 = plain store    (out0[(b*T+t)*2048 + col])
#define NSTAGE   4
#define STG_FLT  9216
#define STG_B    36864
#define GEMM_SMEM (NSTAGE * STG_B)

__global__ __launch_bounds__(256, 1)
void gemm_mma(const float* __restrict__ A, const float* __restrict__ BT,
              float* __restrict__ out0, float* __restrict__ out1, int mode)
{
    extern __shared__ float sm[];
    const uint32_t sbase = smem_u32(sm);

    const int tid  = threadIdx.x;
    const int wid  = tid >> 5;
    const int lane = tid & 31;
    const int wm = wid & 1;
    const int wn = wid >> 1;
    const int g  = lane >> 2;
    const int tg = lane & 3;

    const int bm = blockIdx.y * 128;
    const int bn = blockIdx.x * 128;

    const float* Ab = A  + (size_t)bm * 2048;
    const float* Bb = BT + (size_t)bn * 2048;

    auto load_tile = [&](int kt) {
        int s = kt & 3;
        uint32_t aB = sbase + s * STG_B;
        uint32_t bB = aB + 18432;
        int k0 = kt * 32;
#pragma unroll
        for (int j = 0; j < 4; j++) {
            int c = tid + 256 * j;
            int row = c >> 3, k4 = c & 7;
            cp16(aB + row * 144 + k4 * 16, Ab + (size_t)row * 2048 + k0 + k4 * 4);
        }
#pragma unroll
        for (int j = 0; j < 4; j++) {
            int c = tid + 256 * j;
            int row = c >> 3, k4 = c & 7;
            cp16(bB + row * 144 + k4 * 16, Bb + (size_t)row * 2048 + k0 + k4 * 4);
        }
    };

    float c[4][4][4];
#pragma unroll
    for (int mt = 0; mt < 4; mt++)
#pragma unroll
        for (int nt = 0; nt < 4; nt++)
#pragma unroll
            for (int i = 0; i < 4; i++) c[mt][nt][i] = 0.f;

    load_tile(0); asm volatile("cp.async.commit_group;" ::: "memory");
    load_tile(1); asm volatile("cp.async.commit_group;" ::: "memory");
    load_tile(2); asm volatile("cp.async.commit_group;" ::: "memory");

    for (int it = 0; it < 64; it++) {
        asm volatile("cp.async.wait_group 2;" ::: "memory");
        __syncthreads();

        const float* As = sm + (it & 3) * STG_FLT;
        const float* Bs = As + 4608;

#pragma unroll
        for (int ks = 0; ks < 4; ks++) {
            uint32_t af[4][4], bf[4][2];
#pragma unroll
            for (int mt = 0; mt < 4; mt++) {
                const uint32_t* ap = (const uint32_t*)(As + (wm * 64 + mt * 16 + g) * 36 + ks * 8 + tg);
                af[mt][0] = ap[0];
                af[mt][1] = ap[288];
                af[mt][2] = ap[4];
                af[mt][3] = ap[292];
            }
#pragma unroll
            for (int nt = 0; nt < 4; nt++) {
                const uint32_t* bp = (const uint32_t*)(Bs + (wn * 32 + nt * 8 + g) * 36 + ks * 8 + tg);
                bf[nt][0] = bp[0];
                bf[nt][1] = bp[4];
            }
#pragma unroll
            for (int mt = 0; mt < 4; mt++)
#pragma unroll
                for (int nt = 0; nt < 4; nt++)
                    mma_tf32(c[mt][nt], af[mt], bf[nt]);
        }

        if (it + 3 < 64) load_tile(it + 3);
        asm volatile("cp.async.commit_group;" ::: "memory");
    }

    // ---------------- epilogue ----------------
#pragma unroll
    for (int mt = 0; mt < 4; mt++) {
        int m0 = bm + wm * 64 + mt * 16 + g;
        int m1 = m0 + 8;
        int b0 = m0 >> 11, t0 = m0 & 2047;
        int b1 = m1 >> 11, t1 = m1 & 2047;
#pragma unroll
        for (int nt = 0; nt < 4; nt++) {
            int col = bn + wn * 32 + nt * 8 + tg * 2;
            if (mode == 0) {
                // fused QK: matrix = col>>10 (0 Qsem,1 Ksem,2 Qgeo,3 Kgeo)
                int mat = col >> 10;
                float* dst = (mat & 1) ? out1 : out0;
                int ds = (mat >= 2) ? 64 : 0;
                int h = (col >> 6) & 15, d = col & 63;
                size_t i0 = (((size_t)b0 * NH + h) * T_SEQ + t0) * DCAT + ds + d;
                size_t i1 = (((size_t)b1 * NH + h) * T_SEQ + t1) * DCAT + ds + d;
                *(float2*)&dst[i0] = make_float2(c[mt][nt][0], c[mt][nt][1]);
                *(float2*)&dst[i1] = make_float2(c[mt][nt][2], c[mt][nt][3]);
            } else if (mode == 1) {
                int h = col >> 7, d = col & 127;
                size_t base0 = ((size_t)(b0 * NH + h) * 128 + d) * 2048;
                size_t base1 = ((size_t)(b1 * NH + h) * 128 + d) * 2048;
                out0[base0 + t0]        = c[mt][nt][0];
                out0[base0 + 2048 + t0] = c[mt][nt][1];
                out0[base1 + t1]        = c[mt][nt][2];
                out0[base1 + 2048 + t1] = c[mt][nt][3];
            } else {
                size_t i0 = ((size_t)(b0 * T_SEQ + t0)) * 2048 + col;
                size_t i1 = ((size_t)(b1 * T_SEQ + t1)) * 2048 + col;
                *(float2*)&out0[i0] = make_float2(c[mt][nt][0], c[mt][nt][1]);
                *(float2*)&out0[i1] = make_float2(c[mt][nt][2], c[mt][nt][3]);
            }
        }
    }
}

// ---------------- RoPE + gate folding ----------------
__global__ void rope_gate_kernel(float* __restrict__ Qcat, float* __restrict__ Kcat,
                                 const float* __restrict__ gate_logit,
                                 const int* __restrict__ pos_off)
{
    int row  = blockIdx.x * 4 + (threadIdx.x >> 5);
    int lane = threadIdx.x & 31;

    int t = row % T_SEQ;
    int h = (row / T_SEQ) % NH;

    float g = 1.f / (1.f + expf(-gate_logit[h]));
    float qs_scale = 2.f * g * 0.125f;
    float qg_scale = (2.f - 2.f * g) * 0.125f;

    float freq = powf(10000.f, -(float)lane / 32.f);
    float ang  = (float)(t + pos_off[0]) * freq;
    float c = cosf(ang), s = sinf(ang);

    float* qp = Qcat + (size_t)row * DCAT;
    float* kp = Kcat + (size_t)row * DCAT;

    qp[lane]      *= qs_scale;
    qp[lane + 32] *= qs_scale;

    float x1 = qp[64 + lane], x2 = qp[96 + lane];
    qp[64 + lane] = (x1 * c - x2 * s) * qg_scale;
    qp[96 + lane] = (x2 * c + x1 * s) * qg_scale;

    float k1 = kp[64 + lane], k2 = kp[96 + lane];
    kp[64 + lane] = k1 * c - k2 * s;
    kp[96 + lane] = k2 * c + k1 * s;
}

// ---------------- mma flash attention ----------------
#define FL_QS 0
#define FL_KS 16896
#define FL_VS 25344
#define FL_SS 34048
#define FL_M  42752
#define SMEM_FLASH (43136 * 4)

__global__ __launch_bounds__(256, 1)
void flash_mma(const float* __restrict__ Q, const float* __restrict__ Kc,
               const float* __restrict__ Vt, float* __restrict__ Og)
{
    extern __shared__ float sm[];
    const uint32_t sb = smem_u32(sm);
    float* Qs     = sm + FL_QS;
    float* Ks     = sm + FL_KS;
    float* Vs     = sm + FL_VS;
    float* Ss     = sm + FL_SS;
    float* m_s    = sm + FL_M;
    float* l_s    = m_s + 128;
    float* corr_s = l_s + 128;

    const int qi = gridDim.x - 1 - blockIdx.x;   // longest-first for load balance
    const int bh = blockIdx.y;
    const int q0 = qi * 128;

    const int tid  = threadIdx.x;
    const int wid  = tid >> 5;
    const int lane = tid & 31;
    const int g  = lane >> 2;
    const int tg = lane & 3;
    const int m0 = wid * 16;

    const float* Qb = Q  + ((size_t)bh * T_SEQ + q0) * DCAT;
    const float* Kb = Kc + (size_t)bh * T_SEQ * DCAT;
    const float* Vb = Vt + (size_t)bh * DHEAD * T_SEQ;

    auto loadK = [&](int kt) {
        const float* src = Kb + (size_t)kt * 64 * DCAT;
#pragma unroll
        for (int j = 0; j < 8; j++) {
            int i = tid + 256 * j;
            int r = i >> 5, c4 = i & 31;
            cp16(sb + (FL_KS + r * 132 + c4 * 4) * 4, src + r * DCAT + c4 * 4);
        }
    };
    auto loadV = [&](int kt) {
#pragma unroll
        for (int j = 0; j < 8; j++) {
            int i = tid + 256 * j;
            int d = i >> 4, c4 = i & 15;
            cp16(sb + (FL_VS + d * 68 + c4 * 4) * 4, Vb + (size_t)d * T_SEQ + kt * 64 + c4 * 4);
        }
    };

#pragma unroll
    for (int j = 0; j < 16; j++) {
        int i = tid + 256 * j;
        int r = i >> 5, c4 = i & 31;
        cp16(sb + (FL_QS + r * 132 + c4 * 4) * 4, Qb + (size_t)r * DCAT + c4 * 4);
    }
    loadK(0);
    asm volatile("cp.async.commit_group;" ::: "memory");
    loadV(0);
    asm volatile("cp.async.commit_group;" ::: "memory");

    if (tid < 128) { m_s[tid] = -1e30f; l_s[tid] = 0.f; }

    float of[16][4];
#pragma unroll
    for (int nt = 0; nt < 16; nt++)
#pragma unroll
        for (int i = 0; i < 4; i++) of[nt][i] = 0.f;

    const int nkt = 2 * (qi + 1);

    for (int kt = 0; kt < nkt; kt++) {
        const int k0 = kt * 64;

        asm volatile("cp.async.wait_group 1;" ::: "memory");
        __syncthreads();

        // ---- S = Q K^T, 3-term split tf32 ----
        float sc[8][4];
#pragma unroll
        for (int nt = 0; nt < 8; nt++)
#pragma unroll
            for (int i = 0; i < 4; i++) sc[nt][i] = 0.f;

#pragma unroll
        for (int ks = 0; ks < 16; ks++) {
            const float* ap = Qs + (m0 + g) * 132 + ks * 8 + tg;
            float a0 = ap[0], a1 = ap[8 * 132], a2 = ap[4], a3 = ap[8 * 132 + 4];
            uint32_t ah[4] = {f2tf32(a0), f2tf32(a1), f2tf32(a2), f2tf32(a3)};
            uint32_t al[4] = {f2tf32(a0 - __uint_as_float(ah[0])),
                              f2tf32(a1 - __uint_as_float(ah[1])),
                              f2tf32(a2 - __uint_as_float(ah[2])),
                              f2tf32(a3 - __uint_as_float(ah[3]))};
#pragma unroll
            for (int nt = 0; nt < 8; nt++) {
                const float* bp = Ks + (nt * 8 + g) * 132 + ks * 8 + tg;
                float b0 = bp[0], b1 = bp[4];
                uint32_t bhh[2] = {f2tf32(b0), f2tf32(b1)};
                uint32_t bll[2] = {f2tf32(b0 - __uint_as_float(bhh[0])),
                                   f2tf32(b1 - __uint_as_float(bhh[1]))};
                mma_tf32(sc[nt], ah, bhh);
                mma_tf32(sc[nt], al, bhh);
                mma_tf32(sc[nt], ah, bll);
            }
        }

        const int gr1 = q0 + m0 + g, gr2 = gr1 + 8;
#pragma unroll
        for (int nt = 0; nt < 8; nt++) {
            int gc = k0 + nt * 8 + 2 * tg;
            float v0 = (gc     > gr1) ? -1e30f : sc[nt][0];
            float v1 = (gc + 1 > gr1) ? -1e30f : sc[nt][1];
            float v2 = (gc     > gr2) ? -1e30f : sc[nt][2];
            float v3 = (gc + 1 > gr2) ? -1e30f : sc[nt][3];
            *(float2*)&Ss[(m0 + g) * 68 + nt * 8 + 2 * tg]     = make_float2(v0, v1);
            *(float2*)&Ss[(m0 + g + 8) * 68 + nt * 8 + 2 * tg] = make_float2(v2, v3);
        }
        __syncthreads();

        if (kt + 1 < nkt) loadK(kt + 1);
        asm volatile("cp.async.commit_group;" ::: "memory");

        // ---- online softmax: 2 threads per row ----
        {
            int r = tid >> 1, sub = tid & 1;
            float mold = m_s[r];
            float mx = mold;
            const float* sr = Ss + r * 68 + sub * 32;
#pragma unroll
            for (int j = 0; j < 32; j++) mx = fmaxf(mx, sr[j]);
            mx = fmaxf(mx, __shfl_xor_sync(0xffffffffu, mx, 1));
            float sum = 0.f;
            float* sw = Ss + r * 68 + sub * 32;
#pragma unroll
            for (int j = 0; j < 32; j++) {
                float p = __expf(sw[j] - mx);
                sw[j] = p;
                sum += p;
            }
            sum += __shfl_xor_sync(0xffffffffu, sum, 1);
            if (sub == 0) {
                float corr = __expf(mold - mx);
                l_s[r] = l_s[r] * corr + sum;
                m_s[r] = mx;
                corr_s[r] = corr;
            }
        }
        __syncthreads();

        if (kt + 1 < nkt)
            asm volatile("cp.async.wait_group 1;" ::: "memory");
        else
            asm volatile("cp.async.wait_group 0;" ::: "memory");
        __syncthreads();

        float c1 = corr_s[m0 + g], c2 = corr_s[m0 + g + 8];
#pragma unroll
        for (int nt = 0; nt < 16; nt++) {
            of[nt][0] *= c1; of[nt][1] *= c1;
            of[nt][2] *= c2; of[nt][3] *= c2;
        }

#pragma unroll
        for (int ks = 0; ks < 8; ks++) {
            const float* pp = Ss + (m0 + g) * 68 + ks * 8 + tg;
            float p0 = pp[0], p1 = pp[8 * 68], p2 = pp[4], p3 = pp[8 * 68 + 4];
            uint32_t ph[4] = {f2tf32(p0), f2tf32(p1), f2tf32(p2), f2tf32(p3)};
            uint32_t pl[4] = {f2tf32(p0 - __uint_as_float(ph[0])),
                              f2tf32(p1 - __uint_as_float(ph[1])),
                              f2tf32(p2 - __uint_as_float(ph[2])),
                              f2tf32(p3 - __uint_as_float(ph[3]))};
#pragma unroll
            for (int nt = 0; nt < 16; nt++) {
                const float* vp = Vs + (nt * 8 + g) * 68 + ks * 8 + tg;
                uint32_t bv[2] = {f2tf32(vp[0]), f2tf32(vp[4])};
                mma_tf32(of[nt], ph, bv);
                mma_tf32(of[nt], pl, bv);
            }
        }
        __syncthreads();

        if (kt + 1 < nkt) {
            loadV(kt + 1);
            asm volatile("cp.async.commit_group;" ::: "memory");
        }
    }

    // ---- epilogue: normalize, pre-round to tf32 for the O projection ----
    const int b = bh >> 4, h = bh & 15;
    float il1 = 1.f / l_s[m0 + g];
    float il2 = 1.f / l_s[m0 + g + 8];
    int r1 = q0 + m0 + g, r2 = r1 + 8;
#pragma unroll
    for (int nt = 0; nt < 16; nt++) {
        int col = nt * 8 + 2 * tg;
        size_t i1 = ((size_t)(b * T_SEQ + r1)) * DMODEL + h * DHEAD + col;
        size_t i2 = ((size_t)(b * T_SEQ + r2)) * DMODEL + h * DHEAD + col;
        *(float2*)&Og[i1] = make_float2(f2tf32f(of[nt][0] * il1), f2tf32f(of[nt][1] * il1));
        *(float2*)&Og[i2] = make_float2(f2tf32f(of[nt][2] * il2), f2tf32f(of[nt][3] * il2));
    }
}

// ---------------- launch ----------------
extern "C" void kernel_launch(void* const* d_in, const int* in_sizes, int n_in,
                              void* d_out, int out_size)
{
    const float* x       = (const float*)d_in[0];
    const float* Wq_sem  = (const float*)d_in[1];
    const float* Wk_sem  = (const float*)d_in[2];
    const float* Wq_geo  = (const float*)d_in[3];
    const float* Wk_geo  = (const float*)d_in[4];
    const float* Wv      = (const float*)d_in[5];
    const float* Wo      = (const float*)d_in[6];
    const float* gate    = (const float*)d_in[7];
    const int*   pos_off = (const int*)d_in[8];
    float* out = (float*)d_out;

    float *qcat, *kcat, *vt, *obuf, *wt, *xr;
    cudaGetSymbolAddress((void**)&qcat, g_Qcat);
    cudaGetSymbolAddress((void**)&kcat, g_Kcat);
    cudaGetSymbolAddress((void**)&vt,   g_Vt);
    cudaGetSymbolAddress((void**)&obuf, g_O);
    cudaGetSymbolAddress((void**)&wt,   g_WT);
    cudaGetSymbolAddress((void**)&xr,   g_Xr);

    const size_t SZ_S = 2048u * 1024u;
    // fused QK weight block order: [Qsem | Ksem | Qgeo | Kgeo] along N
    float* wtQK = wt;
    float* wtV  = wt + 4 * SZ_S;
    float* wtO  = wt + 4 * SZ_S + 2048u * 2048u;

    dim3 tb(32, 8);
    transpose_kernel<<<dim3(1024 / 32, 64), tb>>>(Wq_sem, wtQK,             1024);
    transpose_kernel<<<dim3(1024 / 32, 64), tb>>>(Wk_sem, wtQK + SZ_S,      1024);
    transpose_kernel<<<dim3(1024 / 32, 64), tb>>>(Wq_geo, wtQK + 2 * SZ_S,  1024);
    transpose_kernel<<<dim3(1024 / 32, 64), tb>>>(Wk_geo, wtQK + 3 * SZ_S,  1024);
    transpose_kernel<<<dim3(2048 / 32, 64), tb>>>(Wv,     wtV,              2048);
    transpose_kernel<<<dim3(2048 / 32, 64), tb>>>(Wo,     wtO,              2048);

    round_tf32_kernel<<<(BATCH * T_SEQ * DMODEL / 4) / 256, 256>>>(x, xr);

    cudaFuncSetAttribute(gemm_mma, cudaFuncAttributeMaxDynamicSharedMemorySize, GEMM_SMEM);

    // fused QK projections (N=4096) + V projection
    gemm_mma<<<dim3(4096 / 128, 32), 256, GEMM_SMEM>>>(xr, wtQK, qcat, kcat, 0);
    gemm_mma<<<dim3(2048 / 128, 32), 256, GEMM_SMEM>>>(xr, wtV,  vt,   0,    1);

    rope_gate_kernel<<<BATCH * NH * T_SEQ / 4, 128>>>(qcat, kcat, gate, pos_off);

    cudaFuncSetAttribute(flash_mma, cudaFuncAttributeMaxDynamicSharedMemorySize, SMEM_FLASH);
    flash_mma<<<dim3(T_SEQ / 128, BATCH * NH), 256, SMEM_FLASH>>>(qcat, kcat, vt, obuf);

    gemm_mma<<<dim3(2048 / 128, 32), 256, GEMM_SMEM>>>(obuf, wtO, out, 0, 2);
}

// round 6
// speedup vs baseline: 4.3330x; 1.0224x over previous
#include <cuda_runtime.h>
#include <math.h>
#include <stdint.h>

#define T_SEQ  2048
#define BATCH  2
#define DMODEL 2048
#define NH     16
#define DHEAD  128
#define DCAT   128

// ---------------- scratch (device globals: allocation-free) ----------------
__device__ float g_Qcat[(size_t)BATCH * NH * T_SEQ * DCAT];
__device__ float g_Kcat[(size_t)BATCH * NH * T_SEQ * DCAT];
__device__ float g_Vt [(size_t)BATCH * NH * DHEAD * T_SEQ];   // V transposed: [bh][d][t]
__device__ float g_O  [(size_t)BATCH * T_SEQ * DMODEL];
__device__ float g_WT [4u * 2048u * 1024u + 2u * 2048u * 2048u];
__device__ float g_Xr [(size_t)BATCH * T_SEQ * DMODEL];       // x pre-rounded to tf32

// ---------------- helpers ----------------
__device__ __forceinline__ uint32_t smem_u32(const void* p) {
    uint32_t a;
    asm("{ .reg .u64 t; cvta.to.shared.u64 t, %1; cvt.u32.u64 %0, t; }" : "=r"(a) : "l"(p));
    return a;
}
__device__ __forceinline__ void cp16(uint32_t dst, const void* src) {
    asm volatile("cp.async.cg.shared.global [%0], [%1], 16;" :: "r"(dst), "l"(src) : "memory");
}
__device__ __forceinline__ uint32_t f2tf32(float f) {
    uint32_t r;
    asm("cvt.rna.tf32.f32 %0, %1;" : "=r"(r) : "f"(f));
    return r;
}
__device__ __forceinline__ float f2tf32f(float f) { return __uint_as_float(f2tf32(f)); }
__device__ __forceinline__ void mma_tf32(float c[4], const uint32_t a[4], const uint32_t b[2]) {
    asm volatile(
        "mma.sync.aligned.m16n8k8.row.col.f32.tf32.tf32.f32 "
        "{%0,%1,%2,%3}, {%4,%5,%6,%7}, {%8,%9}, {%0,%1,%2,%3};"
        : "+f"(c[0]), "+f"(c[1]), "+f"(c[2]), "+f"(c[3])
        : "r"(a[0]), "r"(a[1]), "r"(a[2]), "r"(a[3]), "r"(b[0]), "r"(b[1]));
}

// ---------------- elementwise tf32 pre-round ----------------
__global__ void round_tf32_kernel(const float* __restrict__ in, float* __restrict__ out)
{
    int i = blockIdx.x * 256 + threadIdx.x;
    float4 v = ((const float4*)in)[i];
    v.x = f2tf32f(v.x); v.y = f2tf32f(v.y); v.z = f2tf32f(v.z); v.w = f2tf32f(v.w);
    ((float4*)out)[i] = v;
}

// ---------------- weight transpose + tf32 round: WT[n][k] = tf32(W[k][n]) ----------------
__global__ void transpose_kernel(const float* __restrict__ W, float* __restrict__ WT, int N)
{
    __shared__ float ts[32][33];
    int n0 = blockIdx.x * 32, k0 = blockIdx.y * 32;
    int x = threadIdx.x, y = threadIdx.y;
#pragma unroll
    for (int i = 0; i < 4; i++)
        ts[y + 8 * i][x] = W[(size_t)(k0 + y + 8 * i) * N + n0 + x];
    __syncthreads();
#pragma unroll
    for (int i = 0; i < 4; i++)
        WT[(size_t)(n0 + y + 8 * i) * 2048 + k0 + x] = f2tf32f(ts[x][y + 8 * i]);
}

// fused 4-matrix version for the QK weights (all N=1024, outputs contiguous)
__global__ void transpose4_kernel(const float* __restrict__ W0, const float* __restrict__ W1,
                                  const float* __restrict__ W2, const float* __restrict__ W3,
                                  float* __restrict__ WT)
{
    __shared__ float ts[32][33];
    const float* W = (blockIdx.z == 0) ? W0 : (blockIdx.z == 1) ? W1 :
                     (blockIdx.z == 2) ? W2 : W3;
    float* dst = WT + (size_t)blockIdx.z * 2048u * 1024u;
    int n0 = blockIdx.x * 32, k0 = blockIdx.y * 32;
    int x = threadIdx.x, y = threadIdx.y;
#pragma unroll
    for (int i = 0; i < 4; i++)
        ts[y + 8 * i][x] = W[(size_t)(k0 + y + 8 * i) * 1024 + n0 + x];
    __syncthreads();
#pragma unroll
    for (int i = 0; i < 4; i++)
        dst[(size_t)(n0 + y + 8 * i) * 2048 + k0 + x] = f2tf32f(ts[x][y + 8 * i]);
}

// ---------------- tf32 HMMA GEMM (128x128 tile, 3-stage cp.async, 2 CTAs/SM) -------
// modes: 0 = fused QK projections (N=4096, out0=qcat, out1=kcat)
//        1 = V projection, transposed store (out0 = Vt[bh][d][t])
//        2 = plain store    (out0[(b*T+t)*2048 + col])
#define STG_FLT  9216
#define STG_B    36864
#define GEMM_SMEM (3 * STG_B)    // 110592 B -> 2 CTAs/SM

__global__ __launch_bounds__(256, 2)
void gemm_mma(const float* __restrict__ A, const float* __restrict__ BT,
              float* __restrict__ out0, float* __restrict__ out1, int mode)
{
    extern __shared__ float sm[];
    const uint32_t sbase = smem_u32(sm);

    const int tid  = threadIdx.x;
    const int wid  = tid >> 5;
    const int lane = tid & 31;
    const int wm = wid & 1;
    const int wn = wid >> 1;
    const int g  = lane >> 2;
    const int tg = lane & 3;

    const int bm = blockIdx.y * 128;
    const int bn = blockIdx.x * 128;

    const float* Ab = A  + (size_t)bm * 2048;
    const float* Bb = BT + (size_t)bn * 2048;

    auto load_tile = [&](int kt) {
        int s = kt % 3;
        uint32_t aB = sbase + s * STG_B;
        uint32_t bB = aB + 18432;
        int k0 = kt * 32;
#pragma unroll
        for (int j = 0; j < 4; j++) {
            int c = tid + 256 * j;
            int row = c >> 3, k4 = c & 7;
            cp16(aB + row * 144 + k4 * 16, Ab + (size_t)row * 2048 + k0 + k4 * 4);
        }
#pragma unroll
        for (int j = 0; j < 4; j++) {
            int c = tid + 256 * j;
            int row = c >> 3, k4 = c & 7;
            cp16(bB + row * 144 + k4 * 16, Bb + (size_t)row * 2048 + k0 + k4 * 4);
        }
    };

    float c[4][4][4];
#pragma unroll
    for (int mt = 0; mt < 4; mt++)
#pragma unroll
        for (int nt = 0; nt < 4; nt++)
#pragma unroll
            for (int i = 0; i < 4; i++) c[mt][nt][i] = 0.f;

    load_tile(0); asm volatile("cp.async.commit_group;" ::: "memory");
    load_tile(1); asm volatile("cp.async.commit_group;" ::: "memory");

    for (int it = 0; it < 64; it++) {
        asm volatile("cp.async.wait_group 1;" ::: "memory");
        __syncthreads();

        // prefetch chunk it+2 into the stage freed by chunk it-1 (all warps done
        // with it-1 thanks to the sync above) BEFORE computing chunk it.
        if (it + 2 < 64) load_tile(it + 2);
        asm volatile("cp.async.commit_group;" ::: "memory");

        const float* As = sm + (it % 3) * STG_FLT;
        const float* Bs = As + 4608;

#pragma unroll
        for (int ks = 0; ks < 4; ks++) {
            uint32_t af[4][4], bf[4][2];
#pragma unroll
            for (int mt = 0; mt < 4; mt++) {
                const uint32_t* ap = (const uint32_t*)(As + (wm * 64 + mt * 16 + g) * 36 + ks * 8 + tg);
                af[mt][0] = ap[0];
                af[mt][1] = ap[288];
                af[mt][2] = ap[4];
                af[mt][3] = ap[292];
            }
#pragma unroll
            for (int nt = 0; nt < 4; nt++) {
                const uint32_t* bp = (const uint32_t*)(Bs + (wn * 32 + nt * 8 + g) * 36 + ks * 8 + tg);
                bf[nt][0] = bp[0];
                bf[nt][1] = bp[4];
            }
#pragma unroll
            for (int mt = 0; mt < 4; mt++)
#pragma unroll
                for (int nt = 0; nt < 4; nt++)
                    mma_tf32(c[mt][nt], af[mt], bf[nt]);
        }
    }

    // ---------------- epilogue ----------------
#pragma unroll
    for (int mt = 0; mt < 4; mt++) {
        int m0 = bm + wm * 64 + mt * 16 + g;
        int m1 = m0 + 8;
        int b0 = m0 >> 11, t0 = m0 & 2047;
        int b1 = m1 >> 11, t1 = m1 & 2047;
#pragma unroll
        for (int nt = 0; nt < 4; nt++) {
            int col = bn + wn * 32 + nt * 8 + tg * 2;
            if (mode == 0) {
                int mat = col >> 10;
                float* dst = (mat & 1) ? out1 : out0;
                int ds = (mat >= 2) ? 64 : 0;
                int h = (col >> 6) & 15, d = col & 63;
                size_t i0 = (((size_t)b0 * NH + h) * T_SEQ + t0) * DCAT + ds + d;
                size_t i1 = (((size_t)b1 * NH + h) * T_SEQ + t1) * DCAT + ds + d;
                *(float2*)&dst[i0] = make_float2(c[mt][nt][0], c[mt][nt][1]);
                *(float2*)&dst[i1] = make_float2(c[mt][nt][2], c[mt][nt][3]);
            } else if (mode == 1) {
                int h = col >> 7, d = col & 127;
                size_t base0 = ((size_t)(b0 * NH + h) * 128 + d) * 2048;
                size_t base1 = ((size_t)(b1 * NH + h) * 128 + d) * 2048;
                out0[base0 + t0]        = c[mt][nt][0];
                out0[base0 + 2048 + t0] = c[mt][nt][1];
                out0[base1 + t1]        = c[mt][nt][2];
                out0[base1 + 2048 + t1] = c[mt][nt][3];
            } else {
                size_t i0 = ((size_t)(b0 * T_SEQ + t0)) * 2048 + col;
                size_t i1 = ((size_t)(b1 * T_SEQ + t1)) * 2048 + col;
                *(float2*)&out0[i0] = make_float2(c[mt][nt][0], c[mt][nt][1]);
                *(float2*)&out0[i1] = make_float2(c[mt][nt][2], c[mt][nt][3]);
            }
        }
    }
}

// ---------------- RoPE + gate folding ----------------
__global__ void rope_gate_kernel(float* __restrict__ Qcat, float* __restrict__ Kcat,
                                 const float* __restrict__ gate_logit,
                                 const int* __restrict__ pos_off)
{
    int row  = blockIdx.x * 4 + (threadIdx.x >> 5);
    int lane = threadIdx.x & 31;

    int t = row % T_SEQ;
    int h = (row / T_SEQ) % NH;

    float g = 1.f / (1.f + expf(-gate_logit[h]));
    float qs_scale = 2.f * g * 0.125f;
    float qg_scale = (2.f - 2.f * g) * 0.125f;

    float freq = powf(10000.f, -(float)lane / 32.f);
    float ang  = (float)(t + pos_off[0]) * freq;
    float c = cosf(ang), s = sinf(ang);

    float* qp = Qcat + (size_t)row * DCAT;
    float* kp = Kcat + (size_t)row * DCAT;

    qp[lane]      *= qs_scale;
    qp[lane + 32] *= qs_scale;

    float x1 = qp[64 + lane], x2 = qp[96 + lane];
    qp[64 + lane] = (x1 * c - x2 * s) * qg_scale;
    qp[96 + lane] = (x2 * c + x1 * s) * qg_scale;

    float k1 = kp[64 + lane], k2 = kp[96 + lane];
    kp[64 + lane] = k1 * c - k2 * s;
    kp[96 + lane] = k2 * c + k1 * s;
}

// ---------------- mma flash attention ----------------
#define FL_QS 0
#define FL_KS 16896
#define FL_VS 25344
#define FL_SS 34048
#define FL_M  42752
#define SMEM_FLASH (43136 * 4)

__global__ __launch_bounds__(256, 1)
void flash_mma(const float* __restrict__ Q, const float* __restrict__ Kc,
               const float* __restrict__ Vt, float* __restrict__ Og)
{
    extern __shared__ float sm[];
    const uint32_t sb = smem_u32(sm);
    float* Qs     = sm + FL_QS;
    float* Ks     = sm + FL_KS;
    float* Vs     = sm + FL_VS;
    float* Ss     = sm + FL_SS;
    float* m_s    = sm + FL_M;
    float* l_s    = m_s + 128;
    float* corr_s = l_s + 128;

    const int qi = gridDim.x - 1 - blockIdx.x;
    const int bh = blockIdx.y;
    const int q0 = qi * 128;

    const int tid  = threadIdx.x;
    const int wid  = tid >> 5;
    const int lane = tid & 31;
    const int g  = lane >> 2;
    const int tg = lane & 3;
    const int m0 = wid * 16;

    const float* Qb = Q  + ((size_t)bh * T_SEQ + q0) * DCAT;
    const float* Kb = Kc + (size_t)bh * T_SEQ * DCAT;
    const float* Vb = Vt + (size_t)bh * DHEAD * T_SEQ;

    auto loadK = [&](int kt) {
        const float* src = Kb + (size_t)kt * 64 * DCAT;
#pragma unroll
        for (int j = 0; j < 8; j++) {
            int i = tid + 256 * j;
            int r = i >> 5, c4 = i & 31;
            cp16(sb + (FL_KS + r * 132 + c4 * 4) * 4, src + r * DCAT + c4 * 4);
        }
    };
    auto loadV = [&](int kt) {
#pragma unroll
        for (int j = 0; j < 8; j++) {
            int i = tid + 256 * j;
            int d = i >> 4, c4 = i & 15;
            cp16(sb + (FL_VS + d * 68 + c4 * 4) * 4, Vb + (size_t)d * T_SEQ + kt * 64 + c4 * 4);
        }
    };

#pragma unroll
    for (int j = 0; j < 16; j++) {
        int i = tid + 256 * j;
        int r = i >> 5, c4 = i & 31;
        cp16(sb + (FL_QS + r * 132 + c4 * 4) * 4, Qb + (size_t)r * DCAT + c4 * 4);
    }
    loadK(0);
    asm volatile("cp.async.commit_group;" ::: "memory");
    loadV(0);
    asm volatile("cp.async.commit_group;" ::: "memory");

    if (tid < 128) { m_s[tid] = -1e30f; l_s[tid] = 0.f; }

    float of[16][4];
#pragma unroll
    for (int nt = 0; nt < 16; nt++)
#pragma unroll
        for (int i = 0; i < 4; i++) of[nt][i] = 0.f;

    const int nkt = 2 * (qi + 1);

    for (int kt = 0; kt < nkt; kt++) {
        const int k0 = kt * 64;

        asm volatile("cp.async.wait_group 1;" ::: "memory");
        __syncthreads();

        // ---- S = Q K^T, 3-term split tf32 ----
        float sc[8][4];
#pragma unroll
        for (int nt = 0; nt < 8; nt++)
#pragma unroll
            for (int i = 0; i < 4; i++) sc[nt][i] = 0.f;

#pragma unroll
        for (int ks = 0; ks < 16; ks++) {
            const float* ap = Qs + (m0 + g) * 132 + ks * 8 + tg;
            float a0 = ap[0], a1 = ap[8 * 132], a2 = ap[4], a3 = ap[8 * 132 + 4];
            uint32_t ah[4] = {f2tf32(a0), f2tf32(a1), f2tf32(a2), f2tf32(a3)};
            uint32_t al[4] = {f2tf32(a0 - __uint_as_float(ah[0])),
                              f2tf32(a1 - __uint_as_float(ah[1])),
                              f2tf32(a2 - __uint_as_float(ah[2])),
                              f2tf32(a3 - __uint_as_float(ah[3]))};
#pragma unroll
            for (int nt = 0; nt < 8; nt++) {
                const float* bp = Ks + (nt * 8 + g) * 132 + ks * 8 + tg;
                float b0 = bp[0], b1 = bp[4];
                uint32_t bhh[2] = {f2tf32(b0), f2tf32(b1)};
                uint32_t bll[2] = {f2tf32(b0 - __uint_as_float(bhh[0])),
                                   f2tf32(b1 - __uint_as_float(bhh[1]))};
                mma_tf32(sc[nt], ah, bhh);
                mma_tf32(sc[nt], al, bhh);
                mma_tf32(sc[nt], ah, bll);
            }
        }

        const int gr1 = q0 + m0 + g, gr2 = gr1 + 8;
#pragma unroll
        for (int nt = 0; nt < 8; nt++) {
            int gc = k0 + nt * 8 + 2 * tg;
            float v0 = (gc     > gr1) ? -1e30f : sc[nt][0];
            float v1 = (gc + 1 > gr1) ? -1e30f : sc[nt][1];
            float v2 = (gc     > gr2) ? -1e30f : sc[nt][2];
            float v3 = (gc + 1 > gr2) ? -1e30f : sc[nt][3];
            *(float2*)&Ss[(m0 + g) * 68 + nt * 8 + 2 * tg]     = make_float2(v0, v1);
            *(float2*)&Ss[(m0 + g + 8) * 68 + nt * 8 + 2 * tg] = make_float2(v2, v3);
        }
        __syncthreads();

        if (kt + 1 < nkt) loadK(kt + 1);
        asm volatile("cp.async.commit_group;" ::: "memory");

        // ---- online softmax: 2 threads per row ----
        {
            int r = tid >> 1, sub = tid & 1;
            float mold = m_s[r];
            float mx = mold;
            const float* sr = Ss + r * 68 + sub * 32;
#pragma unroll
            for (int j = 0; j < 32; j++) mx = fmaxf(mx, sr[j]);
            mx = fmaxf(mx, __shfl_xor_sync(0xffffffffu, mx, 1));
            float sum = 0.f;
            float* sw = Ss + r * 68 + sub * 32;
#pragma unroll
            for (int j = 0; j < 32; j++) {
                float p = __expf(sw[j] - mx);
                sw[j] = p;
                sum += p;
            }
            sum += __shfl_xor_sync(0xffffffffu, sum, 1);
            if (sub == 0) {
                float corr = __expf(mold - mx);
                l_s[r] = l_s[r] * corr + sum;
                m_s[r] = mx;
                corr_s[r] = corr;
            }
        }
        __syncthreads();

        if (kt + 1 < nkt)
            asm volatile("cp.async.wait_group 1;" ::: "memory");
        else
            asm volatile("cp.async.wait_group 0;" ::: "memory");
        __syncthreads();

        float c1 = corr_s[m0 + g], c2 = corr_s[m0 + g + 8];
#pragma unroll
        for (int nt = 0; nt < 16; nt++) {
            of[nt][0] *= c1; of[nt][1] *= c1;
            of[nt][2] *= c2; of[nt][3] *= c2;
        }

#pragma unroll
        for (int ks = 0; ks < 8; ks++) {
            const float* pp = Ss + (m0 + g) * 68 + ks * 8 + tg;
            float p0 = pp[0], p1 = pp[8 * 68], p2 = pp[4], p3 = pp[8 * 68 + 4];
            uint32_t ph[4] = {f2tf32(p0), f2tf32(p1), f2tf32(p2), f2tf32(p3)};
            uint32_t pl[4] = {f2tf32(p0 - __uint_as_float(ph[0])),
                              f2tf32(p1 - __uint_as_float(ph[1])),
                              f2tf32(p2 - __uint_as_float(ph[2])),
                              f2tf32(p3 - __uint_as_float(ph[3]))};
#pragma unroll
            for (int nt = 0; nt < 16; nt++) {
                const float* vp = Vs + (nt * 8 + g) * 68 + ks * 8 + tg;
                uint32_t bv[2] = {f2tf32(vp[0]), f2tf32(vp[4])};
                mma_tf32(of[nt], ph, bv);
                mma_tf32(of[nt], pl, bv);
            }
        }
        __syncthreads();

        if (kt + 1 < nkt) {
            loadV(kt + 1);
            asm volatile("cp.async.commit_group;" ::: "memory");
        }
    }

    // ---- epilogue: normalize, pre-round to tf32 for the O projection ----
    const int b = bh >> 4, h = bh & 15;
    float il1 = 1.f / l_s[m0 + g];
    float il2 = 1.f / l_s[m0 + g + 8];
    int r1 = q0 + m0 + g, r2 = r1 + 8;
#pragma unroll
    for (int nt = 0; nt < 16; nt++) {
        int col = nt * 8 + 2 * tg;
        size_t i1 = ((size_t)(b * T_SEQ + r1)) * DMODEL + h * DHEAD + col;
        size_t i2 = ((size_t)(b * T_SEQ + r2)) * DMODEL + h * DHEAD + col;
        *(float2*)&Og[i1] = make_float2(f2tf32f(of[nt][0] * il1), f2tf32f(of[nt][1] * il1));
        *(float2*)&Og[i2] = make_float2(f2tf32f(of[nt][2] * il2), f2tf32f(of[nt][3] * il2));
    }
}

// ---------------- launch ----------------
extern "C" void kernel_launch(void* const* d_in, const int* in_sizes, int n_in,
                              void* d_out, int out_size)
{
    const float* x       = (const float*)d_in[0];
    const float* Wq_sem  = (const float*)d_in[1];
    const float* Wk_sem  = (const float*)d_in[2];
    const float* Wq_geo  = (const float*)d_in[3];
    const float* Wk_geo  = (const float*)d_in[4];
    const float* Wv      = (const float*)d_in[5];
    const float* Wo      = (const float*)d_in[6];
    const float* gate    = (const float*)d_in[7];
    const int*   pos_off = (const int*)d_in[8];
    float* out = (float*)d_out;

    float *qcat, *kcat, *vt, *obuf, *wt, *xr;
    cudaGetSymbolAddress((void**)&qcat, g_Qcat);
    cudaGetSymbolAddress((void**)&kcat, g_Kcat);
    cudaGetSymbolAddress((void**)&vt,   g_Vt);
    cudaGetSymbolAddress((void**)&obuf, g_O);
    cudaGetSymbolAddress((void**)&wt,   g_WT);
    cudaGetSymbolAddress((void**)&xr,   g_Xr);

    const size_t SZ_S = 2048u * 1024u;
    // fused QK weight block order: [Qsem | Ksem | Qgeo | Kgeo] along N
    float* wtQK = wt;
    float* wtV  = wt + 4 * SZ_S;
    float* wtO  = wt + 4 * SZ_S + 2048u * 2048u;

    dim3 tb(32, 8);
    transpose4_kernel<<<dim3(1024 / 32, 64, 4), tb>>>(Wq_sem, Wk_sem, Wq_geo, Wk_geo, wtQK);
    transpose_kernel<<<dim3(2048 / 32, 64), tb>>>(Wv, wtV, 2048);
    transpose_kernel<<<dim3(2048 / 32, 64), tb>>>(Wo, wtO, 2048);

    round_tf32_kernel<<<(BATCH * T_SEQ * DMODEL / 4) / 256, 256>>>(x, xr);

    cudaFuncSetAttribute(gemm_mma, cudaFuncAttributeMaxDynamicSharedMemorySize, GEMM_SMEM);

    // fused QK projections (N=4096) + V projection
    gemm_mma<<<dim3(4096 / 128, 32), 256, GEMM_SMEM>>>(xr, wtQK, qcat, kcat, 0);
    gemm_mma<<<dim3(2048 / 128, 32), 256, GEMM_SMEM>>>(xr, wtV,  vt,   0,    1);

    rope_gate_kernel<<<BATCH * NH * T_SEQ / 4, 128>>>(qcat, kcat, gate, pos_off);

    cudaFuncSetAttribute(flash_mma, cudaFuncAttributeMaxDynamicSharedMemorySize, SMEM_FLASH);
    flash_mma<<<dim3(T_SEQ / 128, BATCH * NH), 256, SMEM_FLASH>>>(qcat, kcat, vt, obuf);

    gemm_mma<<<dim3(2048 / 128, 32), 256, GEMM_SMEM>>>(obuf, wtO, out, 0, 2);
}

// round 7
// speedup vs baseline: 4.3801x; 1.0109x over previous
#include <cuda_runtime.h>
#include <math.h>
#include <stdint.h>

#define T_SEQ  2048
#define BATCH  2
#define DMODEL 2048
#define NH     16
#define DHEAD  128
#define DCAT   128
#define LOG2E  1.44269504088896340736f

// ---------------- scratch (device globals: allocation-free) ----------------
__device__ float g_Qcat[(size_t)BATCH * NH * T_SEQ * DCAT];
__device__ float g_Kcat[(size_t)BATCH * NH * T_SEQ * DCAT];
__device__ float g_Vt [(size_t)BATCH * NH * DHEAD * T_SEQ];   // V transposed: [bh][d][t]
__device__ float g_O  [(size_t)BATCH * T_SEQ * DMODEL];
__device__ float g_WT [4u * 2048u * 1024u + 2u * 2048u * 2048u];
__device__ float g_Xr [(size_t)BATCH * T_SEQ * DMODEL];       // x pre-rounded to tf32

// ---------------- helpers ----------------
__device__ __forceinline__ uint32_t smem_u32(const void* p) {
    uint32_t a;
    asm("{ .reg .u64 t; cvta.to.shared.u64 t, %1; cvt.u32.u64 %0, t; }" : "=r"(a) : "l"(p));
    return a;
}
__device__ __forceinline__ void cp16(uint32_t dst, const void* src) {
    asm volatile("cp.async.cg.shared.global [%0], [%1], 16;" :: "r"(dst), "l"(src) : "memory");
}
__device__ __forceinline__ uint32_t f2tf32(float f) {
    uint32_t r;
    asm("cvt.rna.tf32.f32 %0, %1;" : "=r"(r) : "f"(f));
    return r;
}
__device__ __forceinline__ float f2tf32f(float f) { return __uint_as_float(f2tf32(f)); }
__device__ __forceinline__ float ex2(float x) {
    float r;
    asm("ex2.approx.f32 %0, %1;" : "=f"(r) : "f"(x));
    return r;
}
__device__ __forceinline__ void mma_tf32(float c[4], const uint32_t a[4], const uint32_t b[2]) {
    asm volatile(
        "mma.sync.aligned.m16n8k8.row.col.f32.tf32.tf32.f32 "
        "{%0,%1,%2,%3}, {%4,%5,%6,%7}, {%8,%9}, {%0,%1,%2,%3};"
        : "+f"(c[0]), "+f"(c[1]), "+f"(c[2]), "+f"(c[3])
        : "r"(a[0]), "r"(a[1]), "r"(a[2]), "r"(a[3]), "r"(b[0]), "r"(b[1]));
}

// ---------------- elementwise tf32 pre-round ----------------
__global__ void round_tf32_kernel(const float* __restrict__ in, float* __restrict__ out)
{
    int i = blockIdx.x * 256 + threadIdx.x;
    float4 v = ((const float4*)in)[i];
    v.x = f2tf32f(v.x); v.y = f2tf32f(v.y); v.z = f2tf32f(v.z); v.w = f2tf32f(v.w);
    ((float4*)out)[i] = v;
}

// ---------------- weight transpose + tf32 round ----------------
__global__ void transpose_kernel(const float* __restrict__ W, float* __restrict__ WT, int N)
{
    __shared__ float ts[32][33];
    int n0 = blockIdx.x * 32, k0 = blockIdx.y * 32;
    int x = threadIdx.x, y = threadIdx.y;
#pragma unroll
    for (int i = 0; i < 4; i++)
        ts[y + 8 * i][x] = W[(size_t)(k0 + y + 8 * i) * N + n0 + x];
    __syncthreads();
#pragma unroll
    for (int i = 0; i < 4; i++)
        WT[(size_t)(n0 + y + 8 * i) * 2048 + k0 + x] = f2tf32f(ts[x][y + 8 * i]);
}

__global__ void transpose4_kernel(const float* __restrict__ W0, const float* __restrict__ W1,
                                  const float* __restrict__ W2, const float* __restrict__ W3,
                                  float* __restrict__ WT)
{
    __shared__ float ts[32][33];
    const float* W = (blockIdx.z == 0) ? W0 : (blockIdx.z == 1) ? W1 :
                     (blockIdx.z == 2) ? W2 : W3;
    float* dst = WT + (size_t)blockIdx.z * 2048u * 1024u;
    int n0 = blockIdx.x * 32, k0 = blockIdx.y * 32;
    int x = threadIdx.x, y = threadIdx.y;
#pragma unroll
    for (int i = 0; i < 4; i++)
        ts[y + 8 * i][x] = W[(size_t)(k0 + y + 8 * i) * 1024 + n0 + x];
    __syncthreads();
#pragma unroll
    for (int i = 0; i < 4; i++)
        dst[(size_t)(n0 + y + 8 * i) * 2048 + k0 + x] = f2tf32f(ts[x][y + 8 * i]);
}

// ---------------- tf32 HMMA GEMM (128x128 tile, 3-stage cp.async, 2 CTAs/SM) -------
#define STG_FLT  9216
#define STG_B    36864
#define GEMM_SMEM (3 * STG_B)

__global__ __launch_bounds__(256, 2)
void gemm_mma(const float* __restrict__ A, const float* __restrict__ BT,
              float* __restrict__ out0, float* __restrict__ out1, int mode)
{
    extern __shared__ float sm[];
    const uint32_t sbase = smem_u32(sm);

    const int tid  = threadIdx.x;
    const int wid  = tid >> 5;
    const int lane = tid & 31;
    const int wm = wid & 1;
    const int wn = wid >> 1;
    const int g  = lane >> 2;
    const int tg = lane & 3;

    const int bm = blockIdx.y * 128;
    const int bn = blockIdx.x * 128;

    const float* Ab = A  + (size_t)bm * 2048;
    const float* Bb = BT + (size_t)bn * 2048;

    auto load_tile = [&](int kt) {
        int s = kt % 3;
        uint32_t aB = sbase + s * STG_B;
        uint32_t bB = aB + 18432;
        int k0 = kt * 32;
#pragma unroll
        for (int j = 0; j < 4; j++) {
            int c = tid + 256 * j;
            int row = c >> 3, k4 = c & 7;
            cp16(aB + row * 144 + k4 * 16, Ab + (size_t)row * 2048 + k0 + k4 * 4);
        }
#pragma unroll
        for (int j = 0; j < 4; j++) {
            int c = tid + 256 * j;
            int row = c >> 3, k4 = c & 7;
            cp16(bB + row * 144 + k4 * 16, Bb + (size_t)row * 2048 + k0 + k4 * 4);
        }
    };

    float c[4][4][4];
#pragma unroll
    for (int mt = 0; mt < 4; mt++)
#pragma unroll
        for (int nt = 0; nt < 4; nt++)
#pragma unroll
            for (int i = 0; i < 4; i++) c[mt][nt][i] = 0.f;

    load_tile(0); asm volatile("cp.async.commit_group;" ::: "memory");
    load_tile(1); asm volatile("cp.async.commit_group;" ::: "memory");

    for (int it = 0; it < 64; it++) {
        asm volatile("cp.async.wait_group 1;" ::: "memory");
        __syncthreads();

        if (it + 2 < 64) load_tile(it + 2);
        asm volatile("cp.async.commit_group;" ::: "memory");

        const float* As = sm + (it % 3) * STG_FLT;
        const float* Bs = As + 4608;

#pragma unroll
        for (int ks = 0; ks < 4; ks++) {
            uint32_t af[4][4], bf[4][2];
#pragma unroll
            for (int mt = 0; mt < 4; mt++) {
                const uint32_t* ap = (const uint32_t*)(As + (wm * 64 + mt * 16 + g) * 36 + ks * 8 + tg);
                af[mt][0] = ap[0];
                af[mt][1] = ap[288];
                af[mt][2] = ap[4];
                af[mt][3] = ap[292];
            }
#pragma unroll
            for (int nt = 0; nt < 4; nt++) {
                const uint32_t* bp = (const uint32_t*)(Bs + (wn * 32 + nt * 8 + g) * 36 + ks * 8 + tg);
                bf[nt][0] = bp[0];
                bf[nt][1] = bp[4];
            }
#pragma unroll
            for (int mt = 0; mt < 4; mt++)
#pragma unroll
                for (int nt = 0; nt < 4; nt++)
                    mma_tf32(c[mt][nt], af[mt], bf[nt]);
        }
    }

#pragma unroll
    for (int mt = 0; mt < 4; mt++) {
        int m0 = bm + wm * 64 + mt * 16 + g;
        int m1 = m0 + 8;
        int b0 = m0 >> 11, t0 = m0 & 2047;
        int b1 = m1 >> 11, t1 = m1 & 2047;
#pragma unroll
        for (int nt = 0; nt < 4; nt++) {
            int col = bn + wn * 32 + nt * 8 + tg * 2;
            if (mode == 0) {
                int mat = col >> 10;
                float* dst = (mat & 1) ? out1 : out0;
                int ds = (mat >= 2) ? 64 : 0;
                int h = (col >> 6) & 15, d = col & 63;
                size_t i0 = (((size_t)b0 * NH + h) * T_SEQ + t0) * DCAT + ds + d;
                size_t i1 = (((size_t)b1 * NH + h) * T_SEQ + t1) * DCAT + ds + d;
                *(float2*)&dst[i0] = make_float2(c[mt][nt][0], c[mt][nt][1]);
                *(float2*)&dst[i1] = make_float2(c[mt][nt][2], c[mt][nt][3]);
            } else if (mode == 1) {
                int h = col >> 7, d = col & 127;
                size_t base0 = ((size_t)(b0 * NH + h) * 128 + d) * 2048;
                size_t base1 = ((size_t)(b1 * NH + h) * 128 + d) * 2048;
                out0[base0 + t0]        = c[mt][nt][0];
                out0[base0 + 2048 + t0] = c[mt][nt][1];
                out0[base1 + t1]        = c[mt][nt][2];
                out0[base1 + 2048 + t1] = c[mt][nt][3];
            } else {
                size_t i0 = ((size_t)(b0 * T_SEQ + t0)) * 2048 + col;
                size_t i1 = ((size_t)(b1 * T_SEQ + t1)) * 2048 + col;
                *(float2*)&out0[i0] = make_float2(c[mt][nt][0], c[mt][nt][1]);
                *(float2*)&out0[i1] = make_float2(c[mt][nt][2], c[mt][nt][3]);
            }
        }
    }
}

// ---------------- RoPE + gate folding (log2e folded into Q scales) ----------------
__global__ void rope_gate_kernel(float* __restrict__ Qcat, float* __restrict__ Kcat,
                                 const float* __restrict__ gate_logit,
                                 const int* __restrict__ pos_off)
{
    int row  = blockIdx.x * 4 + (threadIdx.x >> 5);
    int lane = threadIdx.x & 31;

    int t = row % T_SEQ;
    int h = (row / T_SEQ) % NH;

    float g = 1.f / (1.f + expf(-gate_logit[h]));
    float qs_scale = 2.f * g * 0.125f * LOG2E;
    float qg_scale = (2.f - 2.f * g) * 0.125f * LOG2E;

    float freq = powf(10000.f, -(float)lane / 32.f);
    float ang  = (float)(t + pos_off[0]) * freq;
    float c = cosf(ang), s = sinf(ang);

    float* qp = Qcat + (size_t)row * DCAT;
    float* kp = Kcat + (size_t)row * DCAT;

    qp[lane]      *= qs_scale;
    qp[lane + 32] *= qs_scale;

    float x1 = qp[64 + lane], x2 = qp[96 + lane];
    qp[64 + lane] = (x1 * c - x2 * s) * qg_scale;
    qp[96 + lane] = (x2 * c + x1 * s) * qg_scale;

    float k1 = kp[64 + lane], k2 = kp[96 + lane];
    kp[64 + lane] = k1 * c - k2 * s;
    kp[96 + lane] = k2 * c + k1 * s;
}

// ---------------- mma flash attention, register-resident softmax ----------------
// smem (floats): Qs [128][132] @0, Ks [64][132] @16896, Vs [128][68] @25344,
//                Ss (P) [128][68] @34048 ; total 42752 floats
#define FL_QS 0
#define FL_KS 16896
#define FL_VS 25344
#define FL_SS 34048
#define SMEM_FLASH (42752 * 4)

__global__ __launch_bounds__(256, 1)
void flash_mma(const float* __restrict__ Q, const float* __restrict__ Kc,
               const float* __restrict__ Vt, float* __restrict__ Og)
{
    extern __shared__ float sm[];
    const uint32_t sb = smem_u32(sm);
    float* Qs = sm + FL_QS;
    float* Ks = sm + FL_KS;
    float* Vs = sm + FL_VS;
    float* Ss = sm + FL_SS;

    const int qi = gridDim.x - 1 - blockIdx.x;   // longest-first
    const int bh = blockIdx.y;
    const int q0 = qi * 128;

    const int tid  = threadIdx.x;
    const int wid  = tid >> 5;
    const int lane = tid & 31;
    const int g  = lane >> 2;
    const int tg = lane & 3;
    const int m0 = wid * 16;

    const float* Qb = Q  + ((size_t)bh * T_SEQ + q0) * DCAT;
    const float* Kb = Kc + (size_t)bh * T_SEQ * DCAT;
    const float* Vb = Vt + (size_t)bh * DHEAD * T_SEQ;

    auto loadK = [&](int kt) {
        const float* src = Kb + (size_t)kt * 64 * DCAT;
#pragma unroll
        for (int j = 0; j < 8; j++) {
            int i = tid + 256 * j;
            int r = i >> 5, c4 = i & 31;
            cp16(sb + (FL_KS + r * 132 + c4 * 4) * 4, src + r * DCAT + c4 * 4);
        }
    };
    auto loadV = [&](int kt) {
#pragma unroll
        for (int j = 0; j < 8; j++) {
            int i = tid + 256 * j;
            int d = i >> 4, c4 = i & 15;
            cp16(sb + (FL_VS + d * 68 + c4 * 4) * 4, Vb + (size_t)d * T_SEQ + kt * 64 + c4 * 4);
        }
    };

#pragma unroll
    for (int j = 0; j < 16; j++) {
        int i = tid + 256 * j;
        int r = i >> 5, c4 = i & 31;
        cp16(sb + (FL_QS + r * 132 + c4 * 4) * 4, Qb + (size_t)r * DCAT + c4 * 4);
    }
    loadK(0);
    asm volatile("cp.async.commit_group;" ::: "memory");
    loadV(0);
    asm volatile("cp.async.commit_group;" ::: "memory");

    float of[16][4];
#pragma unroll
    for (int nt = 0; nt < 16; nt++)
#pragma unroll
        for (int i = 0; i < 4; i++) of[nt][i] = 0.f;

    // running softmax state (log2 domain), per-thread (redundant across quad)
    float mrun1 = -1e30f, mrun2 = -1e30f;
    float lrun1 = 0.f,    lrun2 = 0.f;

    const int nkt = 2 * (qi + 1);

    for (int kt = 0; kt < nkt; kt++) {
        const int k0 = kt * 64;

        asm volatile("cp.async.wait_group 1;" ::: "memory");
        __syncthreads();

        // ---- S = Q K^T (log2-domain logits), 3-term split tf32 ----
        float sc[8][4];
#pragma unroll
        for (int nt = 0; nt < 8; nt++)
#pragma unroll
            for (int i = 0; i < 4; i++) sc[nt][i] = 0.f;

#pragma unroll
        for (int ks = 0; ks < 16; ks++) {
            const float* ap = Qs + (m0 + g) * 132 + ks * 8 + tg;
            float a0 = ap[0], a1 = ap[8 * 132], a2 = ap[4], a3 = ap[8 * 132 + 4];
            uint32_t ah[4] = {f2tf32(a0), f2tf32(a1), f2tf32(a2), f2tf32(a3)};
            uint32_t al[4] = {f2tf32(a0 - __uint_as_float(ah[0])),
                              f2tf32(a1 - __uint_as_float(ah[1])),
                              f2tf32(a2 - __uint_as_float(ah[2])),
                              f2tf32(a3 - __uint_as_float(ah[3]))};
#pragma unroll
            for (int nt = 0; nt < 8; nt++) {
                const float* bp = Ks + (nt * 8 + g) * 132 + ks * 8 + tg;
                float b0 = bp[0], b1 = bp[4];
                uint32_t bhh[2] = {f2tf32(b0), f2tf32(b1)};
                uint32_t bll[2] = {f2tf32(b0 - __uint_as_float(bhh[0])),
                                   f2tf32(b1 - __uint_as_float(bhh[1]))};
                mma_tf32(sc[nt], ah, bhh);
                mma_tf32(sc[nt], al, bhh);
                mma_tf32(sc[nt], ah, bll);
            }
        }
        __syncthreads();                 // Ks fully consumed
        if (kt + 1 < nkt) loadK(kt + 1);
        asm volatile("cp.async.commit_group;" ::: "memory");

        // ---- register softmax: mask, row max (quad shfl), exp2, row sum ----
        const int gr1 = q0 + m0 + g, gr2 = gr1 + 8;
        float mx1 = mrun1, mx2 = mrun2;
#pragma unroll
        for (int nt = 0; nt < 8; nt++) {
            int gc = k0 + nt * 8 + 2 * tg;
            if (gc     > gr1) sc[nt][0] = -1e30f;
            if (gc + 1 > gr1) sc[nt][1] = -1e30f;
            if (gc     > gr2) sc[nt][2] = -1e30f;
            if (gc + 1 > gr2) sc[nt][3] = -1e30f;
            mx1 = fmaxf(mx1, fmaxf(sc[nt][0], sc[nt][1]));
            mx2 = fmaxf(mx2, fmaxf(sc[nt][2], sc[nt][3]));
        }
        mx1 = fmaxf(mx1, __shfl_xor_sync(0xffffffffu, mx1, 1));
        mx1 = fmaxf(mx1, __shfl_xor_sync(0xffffffffu, mx1, 2));
        mx2 = fmaxf(mx2, __shfl_xor_sync(0xffffffffu, mx2, 1));
        mx2 = fmaxf(mx2, __shfl_xor_sync(0xffffffffu, mx2, 2));

        float sum1 = 0.f, sum2 = 0.f;
#pragma unroll
        for (int nt = 0; nt < 8; nt++) {
            float p0 = ex2(sc[nt][0] - mx1);
            float p1 = ex2(sc[nt][1] - mx1);
            float p2 = ex2(sc[nt][2] - mx2);
            float p3 = ex2(sc[nt][3] - mx2);
            sum1 += p0 + p1;
            sum2 += p2 + p3;
            *(float2*)&Ss[(m0 + g) * 68 + nt * 8 + 2 * tg]     = make_float2(p0, p1);
            *(float2*)&Ss[(m0 + g + 8) * 68 + nt * 8 + 2 * tg] = make_float2(p2, p3);
        }
        sum1 += __shfl_xor_sync(0xffffffffu, sum1, 1);
        sum1 += __shfl_xor_sync(0xffffffffu, sum1, 2);
        sum2 += __shfl_xor_sync(0xffffffffu, sum2, 1);
        sum2 += __shfl_xor_sync(0xffffffffu, sum2, 2);

        float corr1 = ex2(mrun1 - mx1);
        float corr2 = ex2(mrun2 - mx2);
        lrun1 = lrun1 * corr1 + sum1;
        lrun2 = lrun2 * corr2 + sum2;
        mrun1 = mx1; mrun2 = mx2;
        __syncwarp();                    // P rows visible to own warp

        // ---- wait V(kt) ----
        if (kt + 1 < nkt)
            asm volatile("cp.async.wait_group 1;" ::: "memory");
        else
            asm volatile("cp.async.wait_group 0;" ::: "memory");
        __syncthreads();

        // ---- rescale O, then O += P V (P split, V plain tf32) ----
#pragma unroll
        for (int nt = 0; nt < 16; nt++) {
            of[nt][0] *= corr1; of[nt][1] *= corr1;
            of[nt][2] *= corr2; of[nt][3] *= corr2;
        }

#pragma unroll
        for (int ks = 0; ks < 8; ks++) {
            const float* pp = Ss + (m0 + g) * 68 + ks * 8 + tg;
            float p0 = pp[0], p1 = pp[8 * 68], p2 = pp[4], p3 = pp[8 * 68 + 4];
            uint32_t ph[4] = {f2tf32(p0), f2tf32(p1), f2tf32(p2), f2tf32(p3)};
            uint32_t pl[4] = {f2tf32(p0 - __uint_as_float(ph[0])),
                              f2tf32(p1 - __uint_as_float(ph[1])),
                              f2tf32(p2 - __uint_as_float(ph[2])),
                              f2tf32(p3 - __uint_as_float(ph[3]))};
#pragma unroll
            for (int nt = 0; nt < 16; nt++) {
                const float* vp = Vs + (nt * 8 + g) * 68 + ks * 8 + tg;
                uint32_t bv[2] = {f2tf32(vp[0]), f2tf32(vp[4])};
                mma_tf32(of[nt], ph, bv);
                mma_tf32(of[nt], pl, bv);
            }
        }
        __syncthreads();                 // Vs fully consumed

        if (kt + 1 < nkt) {
            loadV(kt + 1);
            asm volatile("cp.async.commit_group;" ::: "memory");
        }
    }

    // ---- epilogue: normalize, pre-round to tf32 for the O projection ----
    const int b = bh >> 4, h = bh & 15;
    float il1 = 1.f / lrun1;
    float il2 = 1.f / lrun2;
    int r1 = q0 + m0 + g, r2 = r1 + 8;
#pragma unroll
    for (int nt = 0; nt < 16; nt++) {
        int col = nt * 8 + 2 * tg;
        size_t i1 = ((size_t)(b * T_SEQ + r1)) * DMODEL + h * DHEAD + col;
        size_t i2 = ((size_t)(b * T_SEQ + r2)) * DMODEL + h * DHEAD + col;
        *(float2*)&Og[i1] = make_float2(f2tf32f(of[nt][0] * il1), f2tf32f(of[nt][1] * il1));
        *(float2*)&Og[i2] = make_float2(f2tf32f(of[nt][2] * il2), f2tf32f(of[nt][3] * il2));
    }
}

// ---------------- launch ----------------
extern "C" void kernel_launch(void* const* d_in, const int* in_sizes, int n_in,
                              void* d_out, int out_size)
{
    const float* x       = (const float*)d_in[0];
    const float* Wq_sem  = (const float*)d_in[1];
    const float* Wk_sem  = (const float*)d_in[2];
    const float* Wq_geo  = (const float*)d_in[3];
    const float* Wk_geo  = (const float*)d_in[4];
    const float* Wv      = (const float*)d_in[5];
    const float* Wo      = (const float*)d_in[6];
    const float* gate    = (const float*)d_in[7];
    const int*   pos_off = (const int*)d_in[8];
    float* out = (float*)d_out;

    float *qcat, *kcat, *vt, *obuf, *wt, *xr;
    cudaGetSymbolAddress((void**)&qcat, g_Qcat);
    cudaGetSymbolAddress((void**)&kcat, g_Kcat);
    cudaGetSymbolAddress((void**)&vt,   g_Vt);
    cudaGetSymbolAddress((void**)&obuf, g_O);
    cudaGetSymbolAddress((void**)&wt,   g_WT);
    cudaGetSymbolAddress((void**)&xr,   g_Xr);

    const size_t SZ_S = 2048u * 1024u;
    float* wtQK = wt;
    float* wtV  = wt + 4 * SZ_S;
    float* wtO  = wt + 4 * SZ_S + 2048u * 2048u;

    dim3 tb(32, 8);
    transpose4_kernel<<<dim3(1024 / 32, 64, 4), tb>>>(Wq_sem, Wk_sem, Wq_geo, Wk_geo, wtQK);
    transpose_kernel<<<dim3(2048 / 32, 64), tb>>>(Wv, wtV, 2048);
    transpose_kernel<<<dim3(2048 / 32, 64), tb>>>(Wo, wtO, 2048);

    round_tf32_kernel<<<(BATCH * T_SEQ * DMODEL / 4) / 256, 256>>>(x, xr);

    cudaFuncSetAttribute(gemm_mma, cudaFuncAttributeMaxDynamicSharedMemorySize, GEMM_SMEM);

    gemm_mma<<<dim3(4096 / 128, 32), 256, GEMM_SMEM>>>(xr, wtQK, qcat, kcat, 0);
    gemm_mma<<<dim3(2048 / 128, 32), 256, GEMM_SMEM>>>(xr, wtV,  vt,   0,    1);

    rope_gate_kernel<<<BATCH * NH * T_SEQ / 4, 128>>>(qcat, kcat, gate, pos_off);

    cudaFuncSetAttribute(flash_mma, cudaFuncAttributeMaxDynamicSharedMemorySize, SMEM_FLASH);
    flash_mma<<<dim3(T_SEQ / 128, BATCH * NH), 256, SMEM_FLASH>>>(qcat, kcat, vt, obuf);

    gemm_mma<<<dim3(2048 / 128, 32), 256, GEMM_SMEM>>>(obuf, wtO, out, 0, 2);
}

// round 8
// speedup vs baseline: 5.6942x; 1.3000x over previous
#include <cuda_runtime.h>
#include <cuda_fp16.h>
#include <math.h>
#include <stdint.h>

#define T_SEQ  2048
#define BATCH  2
#define DMODEL 2048
#define NH     16
#define DHEAD  128
#define DCAT   128
#define LOG2E  1.44269504088896340736f

// ---------------- scratch (device globals: allocation-free) ----------------
__device__ float  g_Qcat[(size_t)BATCH * NH * T_SEQ * DCAT];
__device__ float  g_Kcat[(size_t)BATCH * NH * T_SEQ * DCAT];
__device__ __half g_Qh[(size_t)BATCH * NH * T_SEQ * DCAT];
__device__ __half g_Ql[(size_t)BATCH * NH * T_SEQ * DCAT];
__device__ __half g_Kh[(size_t)BATCH * NH * T_SEQ * DCAT];
__device__ __half g_Kl[(size_t)BATCH * NH * T_SEQ * DCAT];
__device__ __half g_Vh[(size_t)BATCH * NH * DHEAD * T_SEQ];   // [bh][d][t]
__device__ float  g_O [(size_t)BATCH * T_SEQ * DMODEL];
__device__ float  g_WT [4u * 2048u * 1024u + 2u * 2048u * 2048u];
__device__ float  g_Xr [(size_t)BATCH * T_SEQ * DMODEL];

// ---------------- helpers ----------------
__device__ __forceinline__ uint32_t smem_u32(const void* p) {
    uint32_t a;
    asm("{ .reg .u64 t; cvta.to.shared.u64 t, %1; cvt.u32.u64 %0, t; }" : "=r"(a) : "l"(p));
    return a;
}
__device__ __forceinline__ void cp16(uint32_t dst, const void* src) {
    asm volatile("cp.async.cg.shared.global [%0], [%1], 16;" :: "r"(dst), "l"(src) : "memory");
}
__device__ __forceinline__ uint32_t f2tf32(float f) {
    uint32_t r;
    asm("cvt.rna.tf32.f32 %0, %1;" : "=r"(r) : "f"(f));
    return r;
}
__device__ __forceinline__ float f2tf32f(float f) { return __uint_as_float(f2tf32(f)); }
__device__ __forceinline__ void mma_tf32(float c[4], const uint32_t a[4], const uint32_t b[2]) {
    asm volatile(
        "mma.sync.aligned.m16n8k8.row.col.f32.tf32.tf32.f32 "
        "{%0,%1,%2,%3}, {%4,%5,%6,%7}, {%8,%9}, {%0,%1,%2,%3};"
        : "+f"(c[0]), "+f"(c[1]), "+f"(c[2]), "+f"(c[3])
        : "r"(a[0]), "r"(a[1]), "r"(a[2]), "r"(a[3]), "r"(b[0]), "r"(b[1]));
}
__device__ __forceinline__ void mma_f16(float c[4], const uint32_t a[4], const uint32_t b[2]) {
    asm volatile(
        "mma.sync.aligned.m16n8k16.row.col.f32.f16.f16.f32 "
        "{%0,%1,%2,%3}, {%4,%5,%6,%7}, {%8,%9}, {%0,%1,%2,%3};"
        : "+f"(c[0]), "+f"(c[1]), "+f"(c[2]), "+f"(c[3])
        : "r"(a[0]), "r"(a[1]), "r"(a[2]), "r"(a[3]), "r"(b[0]), "r"(b[1]));
}
// fast exp2 on the FMA pipe (input s <= 0), rel err ~2e-8
__device__ __forceinline__ float fexp2(float s) {
    s = fmaxf(s, -126.f);
    float fl = floorf(s);
    float f = s - fl;
    float p = 1.33336498402e-3f;
    p = fmaf(p, f, 9.81094251585e-3f);
    p = fmaf(p, f, 5.54906469989e-2f);
    p = fmaf(p, f, 2.40230073528e-1f);
    p = fmaf(p, f, 6.93146984780e-1f);
    p = fmaf(p, f, 1.0f);
    int ei = (int)fl;
    return p * __int_as_float((ei + 127) << 23);
}

// ---------------- elementwise tf32 pre-round ----------------
__global__ void round_tf32_kernel(const float* __restrict__ in, float* __restrict__ out)
{
    int i = blockIdx.x * 256 + threadIdx.x;
    float4 v = ((const float4*)in)[i];
    v.x = f2tf32f(v.x); v.y = f2tf32f(v.y); v.z = f2tf32f(v.z); v.w = f2tf32f(v.w);
    ((float4*)out)[i] = v;
}

// ---------------- weight transpose + tf32 round ----------------
__global__ void transpose_kernel(const float* __restrict__ W, float* __restrict__ WT, int N)
{
    __shared__ float ts[32][33];
    int n0 = blockIdx.x * 32, k0 = blockIdx.y * 32;
    int x = threadIdx.x, y = threadIdx.y;
#pragma unroll
    for (int i = 0; i < 4; i++)
        ts[y + 8 * i][x] = W[(size_t)(k0 + y + 8 * i) * N + n0 + x];
    __syncthreads();
#pragma unroll
    for (int i = 0; i < 4; i++)
        WT[(size_t)(n0 + y + 8 * i) * 2048 + k0 + x] = f2tf32f(ts[x][y + 8 * i]);
}

__global__ void transpose4_kernel(const float* __restrict__ W0, const float* __restrict__ W1,
                                  const float* __restrict__ W2, const float* __restrict__ W3,
                                  float* __restrict__ WT)
{
    __shared__ float ts[32][33];
    const float* W = (blockIdx.z == 0) ? W0 : (blockIdx.z == 1) ? W1 :
                     (blockIdx.z == 2) ? W2 : W3;
    float* dst = WT + (size_t)blockIdx.z * 2048u * 1024u;
    int n0 = blockIdx.x * 32, k0 = blockIdx.y * 32;
    int x = threadIdx.x, y = threadIdx.y;
#pragma unroll
    for (int i = 0; i < 4; i++)
        ts[y + 8 * i][x] = W[(size_t)(k0 + y + 8 * i) * 1024 + n0 + x];
    __syncthreads();
#pragma unroll
    for (int i = 0; i < 4; i++)
        dst[(size_t)(n0 + y + 8 * i) * 2048 + k0 + x] = f2tf32f(ts[x][y + 8 * i]);
}

// ---------------- tf32 HMMA GEMM (128x128 tile, 3-stage cp.async) ----------------
// modes: 0 = fused QK projections; 1 = V projection -> fp16 transposed; 2 = plain fp32
#define STG_FLT  9216
#define STG_B    36864
#define GEMM_SMEM (3 * STG_B)

__global__ __launch_bounds__(256, 2)
void gemm_mma(const float* __restrict__ A, const float* __restrict__ BT,
              float* __restrict__ out0, float* __restrict__ out1,
              __half* __restrict__ outh, int mode)
{
    extern __shared__ float sm[];
    const uint32_t sbase = smem_u32(sm);

    const int tid  = threadIdx.x;
    const int wid  = tid >> 5;
    const int lane = tid & 31;
    const int wm = wid & 1;
    const int wn = wid >> 1;
    const int g  = lane >> 2;
    const int tg = lane & 3;

    const int bm = blockIdx.y * 128;
    const int bn = blockIdx.x * 128;

    const float* Ab = A  + (size_t)bm * 2048;
    const float* Bb = BT + (size_t)bn * 2048;

    auto load_tile = [&](int kt) {
        int s = kt % 3;
        uint32_t aB = sbase + s * STG_B;
        uint32_t bB = aB + 18432;
        int k0 = kt * 32;
#pragma unroll
        for (int j = 0; j < 4; j++) {
            int c = tid + 256 * j;
            int row = c >> 3, k4 = c & 7;
            cp16(aB + row * 144 + k4 * 16, Ab + (size_t)row * 2048 + k0 + k4 * 4);
        }
#pragma unroll
        for (int j = 0; j < 4; j++) {
            int c = tid + 256 * j;
            int row = c >> 3, k4 = c & 7;
            cp16(bB + row * 144 + k4 * 16, Bb + (size_t)row * 2048 + k0 + k4 * 4);
        }
    };

    float c[4][4][4];
#pragma unroll
    for (int mt = 0; mt < 4; mt++)
#pragma unroll
        for (int nt = 0; nt < 4; nt++)
#pragma unroll
            for (int i = 0; i < 4; i++) c[mt][nt][i] = 0.f;

    load_tile(0); asm volatile("cp.async.commit_group;" ::: "memory");
    load_tile(1); asm volatile("cp.async.commit_group;" ::: "memory");

    for (int it = 0; it < 64; it++) {
        asm volatile("cp.async.wait_group 1;" ::: "memory");
        __syncthreads();

        if (it + 2 < 64) load_tile(it + 2);
        asm volatile("cp.async.commit_group;" ::: "memory");

        const float* As = sm + (it % 3) * STG_FLT;
        const float* Bs = As + 4608;

#pragma unroll
        for (int ks = 0; ks < 4; ks++) {
            uint32_t af[4][4], bf[4][2];
#pragma unroll
            for (int mt = 0; mt < 4; mt++) {
                const uint32_t* ap = (const uint32_t*)(As + (wm * 64 + mt * 16 + g) * 36 + ks * 8 + tg);
                af[mt][0] = ap[0];
                af[mt][1] = ap[288];
                af[mt][2] = ap[4];
                af[mt][3] = ap[292];
            }
#pragma unroll
            for (int nt = 0; nt < 4; nt++) {
                const uint32_t* bp = (const uint32_t*)(Bs + (wn * 32 + nt * 8 + g) * 36 + ks * 8 + tg);
                bf[nt][0] = bp[0];
                bf[nt][1] = bp[4];
            }
#pragma unroll
            for (int mt = 0; mt < 4; mt++)
#pragma unroll
                for (int nt = 0; nt < 4; nt++)
                    mma_tf32(c[mt][nt], af[mt], bf[nt]);
        }
    }

#pragma unroll
    for (int mt = 0; mt < 4; mt++) {
        int m0 = bm + wm * 64 + mt * 16 + g;
        int m1 = m0 + 8;
        int b0 = m0 >> 11, t0 = m0 & 2047;
        int b1 = m1 >> 11, t1 = m1 & 2047;
#pragma unroll
        for (int nt = 0; nt < 4; nt++) {
            int col = bn + wn * 32 + nt * 8 + tg * 2;
            if (mode == 0) {
                int mat = col >> 10;
                float* dst = (mat & 1) ? out1 : out0;
                int ds = (mat >= 2) ? 64 : 0;
                int h = (col >> 6) & 15, d = col & 63;
                size_t i0 = (((size_t)b0 * NH + h) * T_SEQ + t0) * DCAT + ds + d;
                size_t i1 = (((size_t)b1 * NH + h) * T_SEQ + t1) * DCAT + ds + d;
                *(float2*)&dst[i0] = make_float2(c[mt][nt][0], c[mt][nt][1]);
                *(float2*)&dst[i1] = make_float2(c[mt][nt][2], c[mt][nt][3]);
            } else if (mode == 1) {
                int h = col >> 7, d = col & 127;
                size_t base0 = ((size_t)(b0 * NH + h) * 128 + d) * 2048;
                size_t base1 = ((size_t)(b1 * NH + h) * 128 + d) * 2048;
                outh[base0 + t0]        = __float2half_rn(c[mt][nt][0]);
                outh[base0 + 2048 + t0] = __float2half_rn(c[mt][nt][1]);
                outh[base1 + t1]        = __float2half_rn(c[mt][nt][2]);
                outh[base1 + 2048 + t1] = __float2half_rn(c[mt][nt][3]);
            } else {
                size_t i0 = ((size_t)(b0 * T_SEQ + t0)) * 2048 + col;
                size_t i1 = ((size_t)(b1 * T_SEQ + t1)) * 2048 + col;
                *(float2*)&out0[i0] = make_float2(c[mt][nt][0], c[mt][nt][1]);
                *(float2*)&out0[i1] = make_float2(c[mt][nt][2], c[mt][nt][3]);
            }
        }
    }
}

// ---------------- RoPE + gate folding -> split fp16 Q/K ----------------
__global__ void rope_gate_kernel(const float* __restrict__ Qcat, const float* __restrict__ Kcat,
                                 __half* __restrict__ Qh, __half* __restrict__ Ql,
                                 __half* __restrict__ Kh, __half* __restrict__ Kl,
                                 const float* __restrict__ gate_logit,
                                 const int* __restrict__ pos_off)
{
    int row  = blockIdx.x * 4 + (threadIdx.x >> 5);
    int lane = threadIdx.x & 31;

    int t = row % T_SEQ;
    int h = (row / T_SEQ) % NH;

    float g = 1.f / (1.f + expf(-gate_logit[h]));
    float qs_scale = 2.f * g * 0.125f * LOG2E;
    float qg_scale = (2.f - 2.f * g) * 0.125f * LOG2E;

    float freq = powf(10000.f, -(float)lane / 32.f);
    float ang  = (float)(t + pos_off[0]) * freq;
    float c = cosf(ang), s = sinf(ang);

    const float* qp = Qcat + (size_t)row * DCAT;
    const float* kp = Kcat + (size_t)row * DCAT;
    size_t ob = (size_t)row * DCAT;

    auto wsplit = [&](__half* ah, __half* al, int d, float v) {
        __half hh = __float2half_rn(v);
        ah[ob + d] = hh;
        al[ob + d] = __float2half_rn(v - __half2float(hh));
    };

    wsplit(Qh, Ql, lane,      qp[lane]      * qs_scale);
    wsplit(Qh, Ql, lane + 32, qp[lane + 32] * qs_scale);
    float x1 = qp[64 + lane], x2 = qp[96 + lane];
    wsplit(Qh, Ql, 64 + lane, (x1 * c - x2 * s) * qg_scale);
    wsplit(Qh, Ql, 96 + lane, (x2 * c + x1 * s) * qg_scale);

    wsplit(Kh, Kl, lane,      kp[lane]);
    wsplit(Kh, Kl, lane + 32, kp[lane + 32]);
    float k1 = kp[64 + lane], k2 = kp[96 + lane];
    wsplit(Kh, Kl, 64 + lane, k1 * c - k2 * s);
    wsplit(Kh, Kl, 96 + lane, k2 * c + k1 * s);
}

// ---------------- fp16 mma flash attention (register P, poly exp2) ----------------
// smem in halves: QH[128][136] @0, QL @17408, KH[64][136] @34816, KL @43520,
//                 VH[128][72] @52224; total 61440 halves = 122880 B
#define QH_O 0
#define QL_O 17408
#define KH_O 34816
#define KL_O 43520
#define VH_O 52224
#define SMEM_FLASH (61440 * 2)

__global__ __launch_bounds__(256, 1)
void flash_mma(const __half* __restrict__ Qh, const __half* __restrict__ Ql,
               const __half* __restrict__ Kh, const __half* __restrict__ Kl,
               const __half* __restrict__ Vh, float* __restrict__ Og)
{
    extern __shared__ __half smh[];
    const uint32_t sb = smem_u32(smh);
    const uint32_t* s32 = (const uint32_t*)smh;

    const int qi = gridDim.x - 1 - blockIdx.x;   // longest-first
    const int bh = blockIdx.y;
    const int q0 = qi * 128;

    const int tid  = threadIdx.x;
    const int lane = tid & 31;
    const int g  = lane >> 2;
    const int tg = lane & 3;
    const int m0 = (tid >> 5) * 16;

    const __half* Qbh = Qh + ((size_t)bh * T_SEQ + q0) * DCAT;
    const __half* Qbl = Ql + ((size_t)bh * T_SEQ + q0) * DCAT;
    const __half* Kbh = Kh + (size_t)bh * T_SEQ * DCAT;
    const __half* Kbl = Kl + (size_t)bh * T_SEQ * DCAT;
    const __half* Vb  = Vh + (size_t)bh * DHEAD * T_SEQ;

    auto loadK = [&](int kt) {
        const __half* sh = Kbh + (size_t)kt * 64 * DCAT;
        const __half* sl = Kbl + (size_t)kt * 64 * DCAT;
#pragma unroll
        for (int j = 0; j < 4; j++) {
            int i = tid + 256 * j;
            int r = i >> 4, c8 = i & 15;
            cp16(sb + (KH_O + r * 136 + c8 * 8) * 2, sh + r * DCAT + c8 * 8);
        }
#pragma unroll
        for (int j = 0; j < 4; j++) {
            int i = tid + 256 * j;
            int r = i >> 4, c8 = i & 15;
            cp16(sb + (KL_O + r * 136 + c8 * 8) * 2, sl + r * DCAT + c8 * 8);
        }
    };
    auto loadV = [&](int kt) {
#pragma unroll
        for (int j = 0; j < 4; j++) {
            int i = tid + 256 * j;
            int d = i >> 3, c8 = i & 7;
            cp16(sb + (VH_O + d * 72 + c8 * 8) * 2, Vb + (size_t)d * T_SEQ + kt * 64 + c8 * 8);
        }
    };

#pragma unroll
    for (int j = 0; j < 8; j++) {
        int i = tid + 256 * j;
        int r = i >> 4, c8 = i & 15;
        cp16(sb + (QH_O + r * 136 + c8 * 8) * 2, Qbh + (size_t)r * DCAT + c8 * 8);
    }
#pragma unroll
    for (int j = 0; j < 8; j++) {
        int i = tid + 256 * j;
        int r = i >> 4, c8 = i & 15;
        cp16(sb + (QL_O + r * 136 + c8 * 8) * 2, Qbl + (size_t)r * DCAT + c8 * 8);
    }
    loadK(0);
    asm volatile("cp.async.commit_group;" ::: "memory");
    loadV(0);
    asm volatile("cp.async.commit_group;" ::: "memory");

    float of[16][4];
#pragma unroll
    for (int nt = 0; nt < 16; nt++)
#pragma unroll
        for (int i = 0; i < 4; i++) of[nt][i] = 0.f;

    float mrun1 = -1e30f, mrun2 = -1e30f;
    float lrun1 = 0.f,    lrun2 = 0.f;

    const int nkt = 2 * (qi + 1);

    for (int kt = 0; kt < nkt; kt++) {
        const int k0 = kt * 64;

        asm volatile("cp.async.wait_group 1;" ::: "memory");
        __syncthreads();

        // ---- S = Q K^T : fp16 3-term split (qh*kh + ql*kh + qh*kl) ----
        float sc[8][4];
#pragma unroll
        for (int nt = 0; nt < 8; nt++)
#pragma unroll
            for (int i = 0; i < 4; i++) sc[nt][i] = 0.f;

#pragma unroll
        for (int ks = 0; ks < 8; ks++) {
            int H  = (m0 + g) * 136 + ks * 16 + 2 * tg;
            int H8 = H + 8 * 136;
            uint32_t ah[4] = { s32[(QH_O + H) >> 1], s32[(QH_O + H8) >> 1],
                               s32[(QH_O + H + 8) >> 1], s32[(QH_O + H8 + 8) >> 1] };
            uint32_t al[4] = { s32[(QL_O + H) >> 1], s32[(QL_O + H8) >> 1],
                               s32[(QL_O + H + 8) >> 1], s32[(QL_O + H8 + 8) >> 1] };
#pragma unroll
            for (int nt = 0; nt < 8; nt++) {
                int KB = (nt * 8 + g) * 136 + ks * 16 + 2 * tg;
                uint32_t bh2[2] = { s32[(KH_O + KB) >> 1], s32[(KH_O + KB + 8) >> 1] };
                uint32_t bl2[2] = { s32[(KL_O + KB) >> 1], s32[(KL_O + KB + 8) >> 1] };
                mma_f16(sc[nt], ah, bh2);
                mma_f16(sc[nt], al, bh2);
                mma_f16(sc[nt], ah, bl2);
            }
        }
        __syncthreads();                 // K tiles consumed
        if (kt + 1 < nkt) loadK(kt + 1);
        asm volatile("cp.async.commit_group;" ::: "memory");

        // ---- register softmax (log2 domain, poly exp2 on FMA pipe) ----
        const int gr1 = q0 + m0 + g, gr2 = gr1 + 8;
        float mx1 = mrun1, mx2 = mrun2;
#pragma unroll
        for (int nt = 0; nt < 8; nt++) {
            int gc = k0 + nt * 8 + 2 * tg;
            if (gc     > gr1) sc[nt][0] = -1e30f;
            if (gc + 1 > gr1) sc[nt][1] = -1e30f;
            if (gc     > gr2) sc[nt][2] = -1e30f;
            if (gc + 1 > gr2) sc[nt][3] = -1e30f;
            mx1 = fmaxf(mx1, fmaxf(sc[nt][0], sc[nt][1]));
            mx2 = fmaxf(mx2, fmaxf(sc[nt][2], sc[nt][3]));
        }
        mx1 = fmaxf(mx1, __shfl_xor_sync(0xffffffffu, mx1, 1));
        mx1 = fmaxf(mx1, __shfl_xor_sync(0xffffffffu, mx1, 2));
        mx2 = fmaxf(mx2, __shfl_xor_sync(0xffffffffu, mx2, 1));
        mx2 = fmaxf(mx2, __shfl_xor_sync(0xffffffffu, mx2, 2));

        float sum1 = 0.f, sum2 = 0.f;
#pragma unroll
        for (int nt = 0; nt < 8; nt++) {
            sc[nt][0] = fexp2(sc[nt][0] - mx1);
            sc[nt][1] = fexp2(sc[nt][1] - mx1);
            sc[nt][2] = fexp2(sc[nt][2] - mx2);
            sc[nt][3] = fexp2(sc[nt][3] - mx2);
            sum1 += sc[nt][0] + sc[nt][1];
            sum2 += sc[nt][2] + sc[nt][3];
        }
        sum1 += __shfl_xor_sync(0xffffffffu, sum1, 1);
        sum1 += __shfl_xor_sync(0xffffffffu, sum1, 2);
        sum2 += __shfl_xor_sync(0xffffffffu, sum2, 1);
        sum2 += __shfl_xor_sync(0xffffffffu, sum2, 2);

        float corr1 = fexp2(mrun1 - mx1);
        float corr2 = fexp2(mrun2 - mx2);
        lrun1 = lrun1 * corr1 + sum1;
        lrun2 = lrun2 * corr2 + sum2;
        mrun1 = mx1; mrun2 = mx2;

        // ---- pack P into fp16 A-fragments (registers only) ----
        uint32_t ph[4][4], pl[4][4];
#pragma unroll
        for (int j = 0; j < 4; j++) {
#pragma unroll
            for (int half = 0; half < 2; half++) {   // tiles 2j, 2j+1
                float* p = sc[2 * j + half];
                __half2 h0 = __floats2half2_rn(p[0], p[1]);
                __half2 h1 = __floats2half2_rn(p[2], p[3]);
                float2 f0 = __half22float2(h0);
                float2 f1 = __half22float2(h1);
                __half2 l0 = __floats2half2_rn(p[0] - f0.x, p[1] - f0.y);
                __half2 l1 = __floats2half2_rn(p[2] - f1.x, p[3] - f1.y);
                ph[j][2 * half]     = *(uint32_t*)&h0;
                ph[j][2 * half + 1] = *(uint32_t*)&h1;
                pl[j][2 * half]     = *(uint32_t*)&l0;
                pl[j][2 * half + 1] = *(uint32_t*)&l1;
            }
        }

        // ---- wait V(kt) ----
        if (kt + 1 < nkt)
            asm volatile("cp.async.wait_group 1;" ::: "memory");
        else
            asm volatile("cp.async.wait_group 0;" ::: "memory");
        __syncthreads();

        // ---- rescale O, then O += P V (P 2-term split, V single fp16) ----
#pragma unroll
        for (int nt = 0; nt < 16; nt++) {
            of[nt][0] *= corr1; of[nt][1] *= corr1;
            of[nt][2] *= corr2; of[nt][3] *= corr2;
        }

#pragma unroll
        for (int j = 0; j < 4; j++) {
#pragma unroll
            for (int nt = 0; nt < 16; nt++) {
                int VI = (nt * 8 + g) * 72 + j * 16 + 2 * tg;
                uint32_t bv[2] = { s32[(VH_O + VI) >> 1], s32[(VH_O + VI + 8) >> 1] };
                mma_f16(of[nt], ph[j], bv);
                mma_f16(of[nt], pl[j], bv);
            }
        }
        __syncthreads();                 // V consumed

        if (kt + 1 < nkt) {
            loadV(kt + 1);
            asm volatile("cp.async.commit_group;" ::: "memory");
        }
    }

    // ---- epilogue: normalize, pre-round to tf32 for the O projection ----
    const int b = bh >> 4, h = bh & 15;
    float il1 = 1.f / lrun1;
    float il2 = 1.f / lrun2;
    int r1 = q0 + m0 + g, r2 = r1 + 8;
#pragma unroll
    for (int nt = 0; nt < 16; nt++) {
        int col = nt * 8 + 2 * tg;
        size_t i1 = ((size_t)(b * T_SEQ + r1)) * DMODEL + h * DHEAD + col;
        size_t i2 = ((size_t)(b * T_SEQ + r2)) * DMODEL + h * DHEAD + col;
        *(float2*)&Og[i1] = make_float2(f2tf32f(of[nt][0] * il1), f2tf32f(of[nt][1] * il1));
        *(float2*)&Og[i2] = make_float2(f2tf32f(of[nt][2] * il2), f2tf32f(of[nt][3] * il2));
    }
}

// ---------------- launch ----------------
extern "C" void kernel_launch(void* const* d_in, const int* in_sizes, int n_in,
                              void* d_out, int out_size)
{
    const float* x       = (const float*)d_in[0];
    const float* Wq_sem  = (const float*)d_in[1];
    const float* Wk_sem  = (const float*)d_in[2];
    const float* Wq_geo  = (const float*)d_in[3];
    const float* Wk_geo  = (const float*)d_in[4];
    const float* Wv      = (const float*)d_in[5];
    const float* Wo      = (const float*)d_in[6];
    const float* gate    = (const float*)d_in[7];
    const int*   pos_off = (const int*)d_in[8];
    float* out = (float*)d_out;

    float *qcat, *kcat, *obuf, *wt, *xr;
    __half *qh, *ql, *kh, *kl, *vh;
    cudaGetSymbolAddress((void**)&qcat, g_Qcat);
    cudaGetSymbolAddress((void**)&kcat, g_Kcat);
    cudaGetSymbolAddress((void**)&qh,   g_Qh);
    cudaGetSymbolAddress((void**)&ql,   g_Ql);
    cudaGetSymbolAddress((void**)&kh,   g_Kh);
    cudaGetSymbolAddress((void**)&kl,   g_Kl);
    cudaGetSymbolAddress((void**)&vh,   g_Vh);
    cudaGetSymbolAddress((void**)&obuf, g_O);
    cudaGetSymbolAddress((void**)&wt,   g_WT);
    cudaGetSymbolAddress((void**)&xr,   g_Xr);

    const size_t SZ_S = 2048u * 1024u;
    float* wtQK = wt;
    float* wtV  = wt + 4 * SZ_S;
    float* wtO  = wt + 4 * SZ_S + 2048u * 2048u;

    dim3 tb(32, 8);
    transpose4_kernel<<<dim3(1024 / 32, 64, 4), tb>>>(Wq_sem, Wk_sem, Wq_geo, Wk_geo, wtQK);
    transpose_kernel<<<dim3(2048 / 32, 64), tb>>>(Wv, wtV, 2048);
    transpose_kernel<<<dim3(2048 / 32, 64), tb>>>(Wo, wtO, 2048);

    round_tf32_kernel<<<(BATCH * T_SEQ * DMODEL / 4) / 256, 256>>>(x, xr);

    cudaFuncSetAttribute(gemm_mma, cudaFuncAttributeMaxDynamicSharedMemorySize, GEMM_SMEM);

    gemm_mma<<<dim3(4096 / 128, 32), 256, GEMM_SMEM>>>(xr, wtQK, qcat, kcat, 0, 0);
    gemm_mma<<<dim3(2048 / 128, 32), 256, GEMM_SMEM>>>(xr, wtV,  0, 0, vh, 1);

    rope_gate_kernel<<<BATCH * NH * T_SEQ / 4, 128>>>(qcat, kcat, qh, ql, kh, kl, gate, pos_off);

    cudaFuncSetAttribute(flash_mma, cudaFuncAttributeMaxDynamicSharedMemorySize, SMEM_FLASH);
    flash_mma<<<dim3(T_SEQ / 128, BATCH * NH), 256, SMEM_FLASH>>>(qh, ql, kh, kl, vh, obuf);

    gemm_mma<<<dim3(2048 / 128, 32), 256, GEMM_SMEM>>>(obuf, wtO, out, 0, 0, 2);
}

// round 9
// speedup vs baseline: 7.9599x; 1.3979x over previous
#include <cuda_runtime.h>
#include <cuda_fp16.h>
#include <math.h>
#include <stdint.h>

#define T_SEQ  2048
#define BATCH  2
#define DMODEL 2048
#define NH     16
#define DHEAD  128
#define DCAT   128
#define LOG2E  1.44269504088896340736f

// ---------------- scratch (device globals: allocation-free) ----------------
__device__ float  g_Qcat[(size_t)BATCH * NH * T_SEQ * DCAT];
__device__ float  g_Kcat[(size_t)BATCH * NH * T_SEQ * DCAT];
__device__ __half g_Qh[(size_t)BATCH * NH * T_SEQ * DCAT];
__device__ __half g_Ql[(size_t)BATCH * NH * T_SEQ * DCAT];
__device__ __half g_Kh[(size_t)BATCH * NH * T_SEQ * DCAT];
__device__ __half g_Kl[(size_t)BATCH * NH * T_SEQ * DCAT];
__device__ __half g_Vh[(size_t)BATCH * NH * DHEAD * T_SEQ];   // [bh][d][t]
__device__ __half g_Oh[(size_t)BATCH * T_SEQ * DMODEL];       // attention out (fp16)
__device__ __half g_WTh[4u * 2048u * 1024u + 2u * 2048u * 2048u]; // fp16 transposed weights
__device__ __half g_Xh [(size_t)BATCH * T_SEQ * DMODEL];      // fp16 x

// ---------------- helpers ----------------
__device__ __forceinline__ uint32_t smem_u32(const void* p) {
    uint32_t a;
    asm("{ .reg .u64 t; cvta.to.shared.u64 t, %1; cvt.u32.u64 %0, t; }" : "=r"(a) : "l"(p));
    return a;
}
__device__ __forceinline__ void cp16(uint32_t dst, const void* src) {
    asm volatile("cp.async.cg.shared.global [%0], [%1], 16;" :: "r"(dst), "l"(src) : "memory");
}
__device__ __forceinline__ void mma_f16(float c[4], const uint32_t a[4], const uint32_t b[2]) {
    asm volatile(
        "mma.sync.aligned.m16n8k16.row.col.f32.f16.f16.f32 "
        "{%0,%1,%2,%3}, {%4,%5,%6,%7}, {%8,%9}, {%0,%1,%2,%3};"
        : "+f"(c[0]), "+f"(c[1]), "+f"(c[2]), "+f"(c[3])
        : "r"(a[0]), "r"(a[1]), "r"(a[2]), "r"(a[3]), "r"(b[0]), "r"(b[1]));
}
// fast exp2 on the FMA pipe (input s <= 0), rel err ~2e-8
__device__ __forceinline__ float fexp2(float s) {
    s = fmaxf(s, -126.f);
    float fl = floorf(s);
    float f = s - fl;
    float p = 1.33336498402e-3f;
    p = fmaf(p, f, 9.81094251585e-3f);
    p = fmaf(p, f, 5.54906469989e-2f);
    p = fmaf(p, f, 2.40230073528e-1f);
    p = fmaf(p, f, 6.93146984780e-1f);
    p = fmaf(p, f, 1.0f);
    int ei = (int)fl;
    return p * __int_as_float((ei + 127) << 23);
}

// ---------------- elementwise fp16 convert of x ----------------
__global__ void round_f16_kernel(const float* __restrict__ in, __half* __restrict__ out)
{
    int i = blockIdx.x * 256 + threadIdx.x;
    float4 v = ((const float4*)in)[i];
    __half2 h0 = __floats2half2_rn(v.x, v.y);
    __half2 h1 = __floats2half2_rn(v.z, v.w);
    ((__half2*)out)[2 * i]     = h0;
    ((__half2*)out)[2 * i + 1] = h1;
}

// ---------------- weight transpose + fp16 round: WT[n][k] = h(W[k][n]) ----------------
__global__ void transpose_kernel(const float* __restrict__ W, __half* __restrict__ WT, int N)
{
    __shared__ float ts[32][33];
    int n0 = blockIdx.x * 32, k0 = blockIdx.y * 32;
    int x = threadIdx.x, y = threadIdx.y;
#pragma unroll
    for (int i = 0; i < 4; i++)
        ts[y + 8 * i][x] = W[(size_t)(k0 + y + 8 * i) * N + n0 + x];
    __syncthreads();
#pragma unroll
    for (int i = 0; i < 4; i++)
        WT[(size_t)(n0 + y + 8 * i) * 2048 + k0 + x] = __float2half_rn(ts[x][y + 8 * i]);
}

__global__ void transpose4_kernel(const float* __restrict__ W0, const float* __restrict__ W1,
                                  const float* __restrict__ W2, const float* __restrict__ W3,
                                  __half* __restrict__ WT)
{
    __shared__ float ts[32][33];
    const float* W = (blockIdx.z == 0) ? W0 : (blockIdx.z == 1) ? W1 :
                     (blockIdx.z == 2) ? W2 : W3;
    __half* dst = WT + (size_t)blockIdx.z * 2048u * 1024u;
    int n0 = blockIdx.x * 32, k0 = blockIdx.y * 32;
    int x = threadIdx.x, y = threadIdx.y;
#pragma unroll
    for (int i = 0; i < 4; i++)
        ts[y + 8 * i][x] = W[(size_t)(k0 + y + 8 * i) * 1024 + n0 + x];
    __syncthreads();
#pragma unroll
    for (int i = 0; i < 4; i++)
        dst[(size_t)(n0 + y + 8 * i) * 2048 + k0 + x] = __float2half_rn(ts[x][y + 8 * i]);
}

// ---------------- fp16 HMMA GEMM (128x128 tile, K-chunk 32, 3-stage cp.async) -------
// smem stage: A 128 rows x 40 halves (pad) + B 128 rows x 40 halves = 20480 B
// modes: 0 = fused QK projections (fp32 out0/out1); 1 = V -> fp16 transposed; 2 = plain fp32
#define HSTG_H   10240           // halves per stage
#define HSTG_B   20480           // bytes per stage
#define GEMM_SMEM (3 * HSTG_B)   // 61440 B -> 2+ CTAs/SM

__global__ __launch_bounds__(256, 2)
void gemm_mma(const __half* __restrict__ A, const __half* __restrict__ BT,
              float* __restrict__ out0, float* __restrict__ out1,
              __half* __restrict__ outh, int mode)
{
    extern __shared__ __half smh[];
    const uint32_t sbase = smem_u32(smh);
    const uint32_t* s32 = (const uint32_t*)smh;

    const int tid  = threadIdx.x;
    const int wid  = tid >> 5;
    const int lane = tid & 31;
    const int wm = wid & 1;
    const int wn = wid >> 1;
    const int g  = lane >> 2;
    const int tg = lane & 3;

    const int bm = blockIdx.y * 128;
    const int bn = blockIdx.x * 128;

    const __half* Ab = A  + (size_t)bm * 2048;
    const __half* Bb = BT + (size_t)bn * 2048;

    auto load_tile = [&](int kt) {
        int s = kt % 3;
        uint32_t aB = sbase + s * HSTG_B;
        uint32_t bB = aB + HSTG_B / 2;
        int k0 = kt * 32;
#pragma unroll
        for (int j = 0; j < 2; j++) {
            int idx = tid + 256 * j;
            int row = idx >> 2, c = idx & 3;
            cp16(aB + row * 80 + c * 16, Ab + (size_t)row * 2048 + k0 + c * 8);
        }
#pragma unroll
        for (int j = 0; j < 2; j++) {
            int idx = tid + 256 * j;
            int row = idx >> 2, c = idx & 3;
            cp16(bB + row * 80 + c * 16, Bb + (size_t)row * 2048 + k0 + c * 8);
        }
    };

    float c[4][4][4];
#pragma unroll
    for (int mt = 0; mt < 4; mt++)
#pragma unroll
        for (int nt = 0; nt < 4; nt++)
#pragma unroll
            for (int i = 0; i < 4; i++) c[mt][nt][i] = 0.f;

    load_tile(0); asm volatile("cp.async.commit_group;" ::: "memory");
    load_tile(1); asm volatile("cp.async.commit_group;" ::: "memory");

    for (int it = 0; it < 64; it++) {
        asm volatile("cp.async.wait_group 1;" ::: "memory");
        __syncthreads();

        if (it + 2 < 64) load_tile(it + 2);
        asm volatile("cp.async.commit_group;" ::: "memory");

        const int aH = (it % 3) * HSTG_H;       // half-index of A stage
        const int bH = aH + HSTG_H / 2;

#pragma unroll
        for (int ks = 0; ks < 2; ks++) {
            uint32_t af[4][4], bf[4][2];
#pragma unroll
            for (int mt = 0; mt < 4; mt++) {
                int H = aH + (wm * 64 + mt * 16 + g) * 40 + ks * 16 + 2 * tg;
                af[mt][0] = s32[H >> 1];
                af[mt][1] = s32[(H + 320) >> 1];   // +8 rows
                af[mt][2] = s32[(H + 8) >> 1];
                af[mt][3] = s32[(H + 328) >> 1];
            }
#pragma unroll
            for (int nt = 0; nt < 4; nt++) {
                int H = bH + (wn * 32 + nt * 8 + g) * 40 + ks * 16 + 2 * tg;
                bf[nt][0] = s32[H >> 1];
                bf[nt][1] = s32[(H + 8) >> 1];
            }
#pragma unroll
            for (int mt = 0; mt < 4; mt++)
#pragma unroll
                for (int nt = 0; nt < 4; nt++)
                    mma_f16(c[mt][nt], af[mt], bf[nt]);
        }
    }

    // ---------------- epilogue ----------------
#pragma unroll
    for (int mt = 0; mt < 4; mt++) {
        int m0 = bm + wm * 64 + mt * 16 + g;
        int m1 = m0 + 8;
        int b0 = m0 >> 11, t0 = m0 & 2047;
        int b1 = m1 >> 11, t1 = m1 & 2047;
#pragma unroll
        for (int nt = 0; nt < 4; nt++) {
            int col = bn + wn * 32 + nt * 8 + tg * 2;
            if (mode == 0) {
                int mat = col >> 10;
                float* dst = (mat & 1) ? out1 : out0;
                int ds = (mat >= 2) ? 64 : 0;
                int h = (col >> 6) & 15, d = col & 63;
                size_t i0 = (((size_t)b0 * NH + h) * T_SEQ + t0) * DCAT + ds + d;
                size_t i1 = (((size_t)b1 * NH + h) * T_SEQ + t1) * DCAT + ds + d;
                *(float2*)&dst[i0] = make_float2(c[mt][nt][0], c[mt][nt][1]);
                *(float2*)&dst[i1] = make_float2(c[mt][nt][2], c[mt][nt][3]);
            } else if (mode == 1) {
                int h = col >> 7, d = col & 127;
                size_t base0 = ((size_t)(b0 * NH + h) * 128 + d) * 2048;
                size_t base1 = ((size_t)(b1 * NH + h) * 128 + d) * 2048;
                outh[base0 + t0]        = __float2half_rn(c[mt][nt][0]);
                outh[base0 + 2048 + t0] = __float2half_rn(c[mt][nt][1]);
                outh[base1 + t1]        = __float2half_rn(c[mt][nt][2]);
                outh[base1 + 2048 + t1] = __float2half_rn(c[mt][nt][3]);
            } else {
                size_t i0 = ((size_t)(b0 * T_SEQ + t0)) * 2048 + col;
                size_t i1 = ((size_t)(b1 * T_SEQ + t1)) * 2048 + col;
                *(float2*)&out0[i0] = make_float2(c[mt][nt][0], c[mt][nt][1]);
                *(float2*)&out0[i1] = make_float2(c[mt][nt][2], c[mt][nt][3]);
            }
        }
    }
}

// ---------------- RoPE + gate folding -> split fp16 Q/K ----------------
__global__ void rope_gate_kernel(const float* __restrict__ Qcat, const float* __restrict__ Kcat,
                                 __half* __restrict__ Qh, __half* __restrict__ Ql,
                                 __half* __restrict__ Kh, __half* __restrict__ Kl,
                                 const float* __restrict__ gate_logit,
                                 const int* __restrict__ pos_off)
{
    int row  = blockIdx.x * 4 + (threadIdx.x >> 5);
    int lane = threadIdx.x & 31;

    int t = row % T_SEQ;
    int h = (row / T_SEQ) % NH;

    float g = 1.f / (1.f + expf(-gate_logit[h]));
    float qs_scale = 2.f * g * 0.125f * LOG2E;
    float qg_scale = (2.f - 2.f * g) * 0.125f * LOG2E;

    float freq = powf(10000.f, -(float)lane / 32.f);
    float ang  = (float)(t + pos_off[0]) * freq;
    float c = cosf(ang), s = sinf(ang);

    const float* qp = Qcat + (size_t)row * DCAT;
    const float* kp = Kcat + (size_t)row * DCAT;
    size_t ob = (size_t)row * DCAT;

    auto wsplit = [&](__half* ah, __half* al, int d, float v) {
        __half hh = __float2half_rn(v);
        ah[ob + d] = hh;
        al[ob + d] = __float2half_rn(v - __half2float(hh));
    };

    wsplit(Qh, Ql, lane,      qp[lane]      * qs_scale);
    wsplit(Qh, Ql, lane + 32, qp[lane + 32] * qs_scale);
    float x1 = qp[64 + lane], x2 = qp[96 + lane];
    wsplit(Qh, Ql, 64 + lane, (x1 * c - x2 * s) * qg_scale);
    wsplit(Qh, Ql, 96 + lane, (x2 * c + x1 * s) * qg_scale);

    wsplit(Kh, Kl, lane,      kp[lane]);
    wsplit(Kh, Kl, lane + 32, kp[lane + 32]);
    float k1 = kp[64 + lane], k2 = kp[96 + lane];
    wsplit(Kh, Kl, 64 + lane, k1 * c - k2 * s);
    wsplit(Kh, Kl, 96 + lane, k2 * c + k1 * s);
}

// ---------------- fp16 mma flash attention (register P, poly exp2) ----------------
#define QH_O 0
#define QL_O 17408
#define KH_O 34816
#define KL_O 43520
#define VH_O 52224
#define SMEM_FLASH (61440 * 2)

__global__ __launch_bounds__(256, 1)
void flash_mma(const __half* __restrict__ Qh, const __half* __restrict__ Ql,
               const __half* __restrict__ Kh, const __half* __restrict__ Kl,
               const __half* __restrict__ Vh, __half* __restrict__ Og)
{
    extern __shared__ __half smh[];
    const uint32_t sb = smem_u32(smh);
    const uint32_t* s32 = (const uint32_t*)smh;

    const int qi = gridDim.x - 1 - blockIdx.x;   // longest-first
    const int bh = blockIdx.y;
    const int q0 = qi * 128;

    const int tid  = threadIdx.x;
    const int lane = tid & 31;
    const int g  = lane >> 2;
    const int tg = lane & 3;
    const int m0 = (tid >> 5) * 16;

    const __half* Qbh = Qh + ((size_t)bh * T_SEQ + q0) * DCAT;
    const __half* Qbl = Ql + ((size_t)bh * T_SEQ + q0) * DCAT;
    const __half* Kbh = Kh + (size_t)bh * T_SEQ * DCAT;
    const __half* Kbl = Kl + (size_t)bh * T_SEQ * DCAT;
    const __half* Vb  = Vh + (size_t)bh * DHEAD * T_SEQ;

    auto loadK = [&](int kt) {
        const __half* sh = Kbh + (size_t)kt * 64 * DCAT;
        const __half* sl = Kbl + (size_t)kt * 64 * DCAT;
#pragma unroll
        for (int j = 0; j < 4; j++) {
            int i = tid + 256 * j;
            int r = i >> 4, c8 = i & 15;
            cp16(sb + (KH_O + r * 136 + c8 * 8) * 2, sh + r * DCAT + c8 * 8);
        }
#pragma unroll
        for (int j = 0; j < 4; j++) {
            int i = tid + 256 * j;
            int r = i >> 4, c8 = i & 15;
            cp16(sb + (KL_O + r * 136 + c8 * 8) * 2, sl + r * DCAT + c8 * 8);
        }
    };
    auto loadV = [&](int kt) {
#pragma unroll
        for (int j = 0; j < 4; j++) {
            int i = tid + 256 * j;
            int d = i >> 3, c8 = i & 7;
            cp16(sb + (VH_O + d * 72 + c8 * 8) * 2, Vb + (size_t)d * T_SEQ + kt * 64 + c8 * 8);
        }
    };

#pragma unroll
    for (int j = 0; j < 8; j++) {
        int i = tid + 256 * j;
        int r = i >> 4, c8 = i & 15;
        cp16(sb + (QH_O + r * 136 + c8 * 8) * 2, Qbh + (size_t)r * DCAT + c8 * 8);
    }
#pragma unroll
    for (int j = 0; j < 8; j++) {
        int i = tid + 256 * j;
        int r = i >> 4, c8 = i & 15;
        cp16(sb + (QL_O + r * 136 + c8 * 8) * 2, Qbl + (size_t)r * DCAT + c8 * 8);
    }
    loadK(0);
    asm volatile("cp.async.commit_group;" ::: "memory");
    loadV(0);
    asm volatile("cp.async.commit_group;" ::: "memory");

    float of[16][4];
#pragma unroll
    for (int nt = 0; nt < 16; nt++)
#pragma unroll
        for (int i = 0; i < 4; i++) of[nt][i] = 0.f;

    float mrun1 = -1e30f, mrun2 = -1e30f;
    float lrun1 = 0.f,    lrun2 = 0.f;

    const int nkt = 2 * (qi + 1);

    for (int kt = 0; kt < nkt; kt++) {
        const int k0 = kt * 64;

        asm volatile("cp.async.wait_group 1;" ::: "memory");
        __syncthreads();

        // ---- S = Q K^T : fp16 3-term split ----
        float sc[8][4];
#pragma unroll
        for (int nt = 0; nt < 8; nt++)
#pragma unroll
            for (int i = 0; i < 4; i++) sc[nt][i] = 0.f;

#pragma unroll
        for (int ks = 0; ks < 8; ks++) {
            int H  = (m0 + g) * 136 + ks * 16 + 2 * tg;
            int H8 = H + 8 * 136;
            uint32_t ah[4] = { s32[(QH_O + H) >> 1], s32[(QH_O + H8) >> 1],
                               s32[(QH_O + H + 8) >> 1], s32[(QH_O + H8 + 8) >> 1] };
            uint32_t al[4] = { s32[(QL_O + H) >> 1], s32[(QL_O + H8) >> 1],
                               s32[(QL_O + H + 8) >> 1], s32[(QL_O + H8 + 8) >> 1] };
#pragma unroll
            for (int nt = 0; nt < 8; nt++) {
                int KB = (nt * 8 + g) * 136 + ks * 16 + 2 * tg;
                uint32_t bh2[2] = { s32[(KH_O + KB) >> 1], s32[(KH_O + KB + 8) >> 1] };
                uint32_t bl2[2] = { s32[(KL_O + KB) >> 1], s32[(KL_O + KB + 8) >> 1] };
                mma_f16(sc[nt], ah, bh2);
                mma_f16(sc[nt], al, bh2);
                mma_f16(sc[nt], ah, bl2);
            }
        }
        __syncthreads();
        if (kt + 1 < nkt) loadK(kt + 1);
        asm volatile("cp.async.commit_group;" ::: "memory");

        // ---- register softmax ----
        const int gr1 = q0 + m0 + g, gr2 = gr1 + 8;
        float mx1 = mrun1, mx2 = mrun2;
#pragma unroll
        for (int nt = 0; nt < 8; nt++) {
            int gc = k0 + nt * 8 + 2 * tg;
            if (gc     > gr1) sc[nt][0] = -1e30f;
            if (gc + 1 > gr1) sc[nt][1] = -1e30f;
            if (gc     > gr2) sc[nt][2] = -1e30f;
            if (gc + 1 > gr2) sc[nt][3] = -1e30f;
            mx1 = fmaxf(mx1, fmaxf(sc[nt][0], sc[nt][1]));
            mx2 = fmaxf(mx2, fmaxf(sc[nt][2], sc[nt][3]));
        }
        mx1 = fmaxf(mx1, __shfl_xor_sync(0xffffffffu, mx1, 1));
        mx1 = fmaxf(mx1, __shfl_xor_sync(0xffffffffu, mx1, 2));
        mx2 = fmaxf(mx2, __shfl_xor_sync(0xffffffffu, mx2, 1));
        mx2 = fmaxf(mx2, __shfl_xor_sync(0xffffffffu, mx2, 2));

        float sum1 = 0.f, sum2 = 0.f;
#pragma unroll
        for (int nt = 0; nt < 8; nt++) {
            sc[nt][0] = fexp2(sc[nt][0] - mx1);
            sc[nt][1] = fexp2(sc[nt][1] - mx1);
            sc[nt][2] = fexp2(sc[nt][2] - mx2);
            sc[nt][3] = fexp2(sc[nt][3] - mx2);
            sum1 += sc[nt][0] + sc[nt][1];
            sum2 += sc[nt][2] + sc[nt][3];
        }
        sum1 += __shfl_xor_sync(0xffffffffu, sum1, 1);
        sum1 += __shfl_xor_sync(0xffffffffu, sum1, 2);
        sum2 += __shfl_xor_sync(0xffffffffu, sum2, 1);
        sum2 += __shfl_xor_sync(0xffffffffu, sum2, 2);

        float corr1 = fexp2(mrun1 - mx1);
        float corr2 = fexp2(mrun2 - mx2);
        lrun1 = lrun1 * corr1 + sum1;
        lrun2 = lrun2 * corr2 + sum2;
        mrun1 = mx1; mrun2 = mx2;

        // ---- pack P into fp16 A-fragments (registers only) ----
        uint32_t ph[4][4], pl[4][4];
#pragma unroll
        for (int j = 0; j < 4; j++) {
#pragma unroll
            for (int hf = 0; hf < 2; hf++) {
                float* p = sc[2 * j + hf];
                __half2 h0 = __floats2half2_rn(p[0], p[1]);
                __half2 h1 = __floats2half2_rn(p[2], p[3]);
                float2 f0 = __half22float2(h0);
                float2 f1 = __half22float2(h1);
                __half2 l0 = __floats2half2_rn(p[0] - f0.x, p[1] - f0.y);
                __half2 l1 = __floats2half2_rn(p[2] - f1.x, p[3] - f1.y);
                ph[j][2 * hf]     = *(uint32_t*)&h0;
                ph[j][2 * hf + 1] = *(uint32_t*)&h1;
                pl[j][2 * hf]     = *(uint32_t*)&l0;
                pl[j][2 * hf + 1] = *(uint32_t*)&l1;
            }
        }

        if (kt + 1 < nkt)
            asm volatile("cp.async.wait_group 1;" ::: "memory");
        else
            asm volatile("cp.async.wait_group 0;" ::: "memory");
        __syncthreads();

        // ---- rescale O, then O += P V ----
#pragma unroll
        for (int nt = 0; nt < 16; nt++) {
            of[nt][0] *= corr1; of[nt][1] *= corr1;
            of[nt][2] *= corr2; of[nt][3] *= corr2;
        }

#pragma unroll
        for (int j = 0; j < 4; j++) {
#pragma unroll
            for (int nt = 0; nt < 16; nt++) {
                int VI = (nt * 8 + g) * 72 + j * 16 + 2 * tg;
                uint32_t bv[2] = { s32[(VH_O + VI) >> 1], s32[(VH_O + VI + 8) >> 1] };
                mma_f16(of[nt], ph[j], bv);
                mma_f16(of[nt], pl[j], bv);
            }
        }
        __syncthreads();

        if (kt + 1 < nkt) {
            loadV(kt + 1);
            asm volatile("cp.async.commit_group;" ::: "memory");
        }
    }

    // ---- epilogue: normalize, write fp16 for the O projection ----
    const int b = bh >> 4, h = bh & 15;
    float il1 = 1.f / lrun1;
    float il2 = 1.f / lrun2;
    int r1 = q0 + m0 + g, r2 = r1 + 8;
#pragma unroll
    for (int nt = 0; nt < 16; nt++) {
        int col = nt * 8 + 2 * tg;
        size_t i1 = ((size_t)(b * T_SEQ + r1)) * DMODEL + h * DHEAD + col;
        size_t i2 = ((size_t)(b * T_SEQ + r2)) * DMODEL + h * DHEAD + col;
        *(__half2*)&Og[i1] = __floats2half2_rn(of[nt][0] * il1, of[nt][1] * il1);
        *(__half2*)&Og[i2] = __floats2half2_rn(of[nt][2] * il2, of[nt][3] * il2);
    }
}

// ---------------- launch ----------------
extern "C" void kernel_launch(void* const* d_in, const int* in_sizes, int n_in,
                              void* d_out, int out_size)
{
    const float* x       = (const float*)d_in[0];
    const float* Wq_sem  = (const float*)d_in[1];
    const float* Wk_sem  = (const float*)d_in[2];
    const float* Wq_geo  = (const float*)d_in[3];
    const float* Wk_geo  = (const float*)d_in[4];
    const float* Wv      = (const float*)d_in[5];
    const float* Wo      = (const float*)d_in[6];
    const float* gate    = (const float*)d_in[7];
    const int*   pos_off = (const int*)d_in[8];
    float* out = (float*)d_out;

    float *qcat, *kcat;
    __half *qh, *ql, *kh, *kl, *vh, *obufh, *wth, *xh;
    cudaGetSymbolAddress((void**)&qcat,  g_Qcat);
    cudaGetSymbolAddress((void**)&kcat,  g_Kcat);
    cudaGetSymbolAddress((void**)&qh,    g_Qh);
    cudaGetSymbolAddress((void**)&ql,    g_Ql);
    cudaGetSymbolAddress((void**)&kh,    g_Kh);
    cudaGetSymbolAddress((void**)&kl,    g_Kl);
    cudaGetSymbolAddress((void**)&vh,    g_Vh);
    cudaGetSymbolAddress((void**)&obufh, g_Oh);
    cudaGetSymbolAddress((void**)&wth,   g_WTh);
    cudaGetSymbolAddress((void**)&xh,    g_Xh);

    const size_t SZ_S = 2048u * 1024u;
    __half* wtQK = wth;
    __half* wtV  = wth + 4 * SZ_S;
    __half* wtO  = wth + 4 * SZ_S + 2048u * 2048u;

    dim3 tb(32, 8);
    transpose4_kernel<<<dim3(1024 / 32, 64, 4), tb>>>(Wq_sem, Wk_sem, Wq_geo, Wk_geo, wtQK);
    transpose_kernel<<<dim3(2048 / 32, 64), tb>>>(Wv, wtV, 2048);
    transpose_kernel<<<dim3(2048 / 32, 64), tb>>>(Wo, wtO, 2048);

    round_f16_kernel<<<(BATCH * T_SEQ * DMODEL / 4) / 256, 256>>>(x, xh);

    cudaFuncSetAttribute(gemm_mma, cudaFuncAttributeMaxDynamicSharedMemorySize, GEMM_SMEM);

    gemm_mma<<<dim3(4096 / 128, 32), 256, GEMM_SMEM>>>(xh, wtQK, qcat, kcat, 0, 0);
    gemm_mma<<<dim3(2048 / 128, 32), 256, GEMM_SMEM>>>(xh, wtV,  0, 0, vh, 1);

    rope_gate_kernel<<<BATCH * NH * T_SEQ / 4, 128>>>(qcat, kcat, qh, ql, kh, kl, gate, pos_off);

    cudaFuncSetAttribute(flash_mma, cudaFuncAttributeMaxDynamicSharedMemorySize, SMEM_FLASH);
    flash_mma<<<dim3(T_SEQ / 128, BATCH * NH), 256, SMEM_FLASH>>>(qh, ql, kh, kl, vh, obufh);

    gemm_mma<<<dim3(2048 / 128, 32), 256, GEMM_SMEM>>>(obufh, wtO, out, 0, 0, 2);
}